// round 6
// baseline (speedup 1.0000x reference)
#include <cuda_runtime.h>
#include <math.h>
#include <stdint.h>

// Problem constants
#define BB   32
#define NN_  1024
#define DD   256
#define HH   256
#define EE   256
#define CC   256
#define KTOP 128
#define TEMPR 0.1f

// ---------------- scratch (device globals; no allocation allowed) ----------------
__device__ float g_deg[BB * NN_];
__device__ float g_agg[BB * NN_ * DD];       // 32 MB
__device__ float g_pre[BB * NN_ * HH];       // 32 MB
__device__ float g_sTa[BB * CC * NN_];       // 32 MB
__device__ float g_sts[BB * CC * CC];        // 8 MB
__device__ float g_U[BB * CC * CC];          // 8 MB
__device__ float g_V[BB * CC * CC];          // 8 MB
__device__ float g_scores[BB * CC];
__device__ float g_thresh[BB];
__device__ double g_sumsq_adj;
__device__ double g_ent;
__device__ double g_trA[BB], g_ssA[BB], g_trG[BB], g_ssG[BB], g_dotUV[BB];

// ---------------- helpers ----------------
__device__ __forceinline__ double block_red_d(double v, double* sm) {
    int t = threadIdx.x;
    sm[t] = v; __syncthreads();
    for (int o = 128; o > 0; o >>= 1) {
        if (t < o) sm[t] += sm[t + o];
        __syncthreads();
    }
    double r = sm[0]; __syncthreads();
    return r;
}

__device__ __forceinline__ void cp16(void* s, const void* g) {
    uint32_t si = (uint32_t)__cvta_generic_to_shared(s);
    asm volatile("cp.async.cg.shared.global [%0], [%1], 16;\n" :: "r"(si), "l"(g));
}
__device__ __forceinline__ void cp_commit() {
    asm volatile("cp.async.commit_group;\n" ::);
}

// tf32 hi/lo split: f = hi + lo (+ ~2^-23 f), both tf32-rounded fp32 patterns
__device__ __forceinline__ void tf32_split(float f, uint32_t& hi, uint32_t& lo) {
    asm("cvt.rna.tf32.f32 %0, %1;" : "=r"(hi) : "f"(f));
    float r = f - __uint_as_float(hi);
    asm("cvt.rna.tf32.f32 %0, %1;" : "=r"(lo) : "f"(r));
}

// D += A(tf32) * B(tf32), m16n8k8
__device__ __forceinline__ void mma8(float* d, const uint32_t* a, const uint32_t* b) {
    asm volatile(
        "mma.sync.aligned.m16n8k8.row.col.f32.tf32.tf32.f32 "
        "{%0,%1,%2,%3},{%4,%5,%6,%7},{%8,%9},{%0,%1,%2,%3};"
        : "+f"(d[0]), "+f"(d[1]), "+f"(d[2]), "+f"(d[3])
        : "r"(a[0]), "r"(a[1]), "r"(a[2]), "r"(a[3]), "r"(b[0]), "r"(b[1]));
}

__global__ void init_kernel() {
    int i = blockIdx.x * blockDim.x + threadIdx.x;
    if (i < BB * CC) g_scores[i] = 0.0f;
    if (i == 0) { g_sumsq_adj = 0.0; g_ent = 0.0; }
}

// degree: deg[b,n] = max(1, sum_m adj[b,n,m])
__global__ void deg_kernel(const float* __restrict__ adj) {
    int row = blockIdx.x;
    const float* a = adj + (size_t)row * NN_;
    float s = 0.f;
    for (int i = threadIdx.x; i < NN_; i += 256) s += a[i];
    __shared__ float sm[256];
    sm[threadIdx.x] = s; __syncthreads();
    for (int o = 128; o > 0; o >>= 1) {
        if (threadIdx.x < o) sm[threadIdx.x] += sm[threadIdx.x + o];
        __syncthreads();
    }
    if (threadIdx.x == 0) g_deg[row] = fmaxf(sm[0], 1.0f);
}

// ---------------- tensor-core 128x128x16 GEMM, tf32 3x split, cp.async pipelined ----
// C = op(A)@B [+ op2(A2)@B2] [+bias][/rowdiv]
// TA=false: A is [M,K] row-major. TA=true: A is [K,M] row-major.
// B is [K,N] row-major. M,N multiples of 128; K multiple of 16.
// 8 warps = 2(m) x 4(n); warp tile 64x32 = 4x4 m16n8 fragments.
template<bool TA>
__global__ __launch_bounds__(256) void gemm128(
    const float* __restrict__ A, const float* __restrict__ Bm,
    float* __restrict__ Cm,
    const float* __restrict__ A2, const float* __restrict__ B2,
    const float* __restrict__ bias, const float* __restrict__ rowdiv,
    int M, int Nn, int Kd, size_t sA, size_t sB, size_t sC)
{
    constexpr int BP  = 136;                         // B smem pitch (floats)
    constexpr int ASZ = TA ? (16 * 136) : (128 * 20);
    __shared__ float As[2][ASZ];
    __shared__ float Bs[2][16 * BP];

    int bz = blockIdx.z;
    int bm = blockIdx.y * 128, bn = blockIdx.x * 128;
    int tid = threadIdx.x;
    int lane = tid & 31, wid = tid >> 5;
    int g = lane >> 2, tg = lane & 3;                // groupID, thread-in-group
    int mw = (wid & 1) * 64, nw = (wid >> 1) * 32;   // warp tile origin

    const float* Ab1 = A  + (size_t)bz * sA;
    const float* Bb1 = Bm + (size_t)bz * sB;
    const float* Ab2 = A2 ? A2 + (size_t)bz * sA : nullptr;
    const float* Bb2 = A2 ? B2 + (size_t)bz * sB : nullptr;
    const int T1 = Kd / 16;
    const int T  = A2 ? 2 * T1 : T1;

    auto issue = [&](int t, int buf) {
        const float* Ap; const float* Bp; int k0;
        if (t < T1) { Ap = Ab1; Bp = Bb1; k0 = t * 16; }
        else        { Ap = Ab2; Bp = Bb2; k0 = (t - T1) * 16; }
        #pragma unroll
        for (int i = 0; i < 2; i++) {                // B tile [16][BP]
            int id = tid * 2 + i;
            int r = id >> 5, c = (id & 31) * 4;
            cp16(&Bs[buf][r * BP + c], Bp + (size_t)(k0 + r) * Nn + bn + c);
        }
        if (TA) {
            #pragma unroll
            for (int i = 0; i < 2; i++) {            // A tile [16][136] (k-major)
                int id = tid * 2 + i;
                int r = id >> 5, c = (id & 31) * 4;
                cp16(&As[buf][r * 136 + c], Ap + (size_t)(k0 + r) * M + bm + c);
            }
        } else {
            #pragma unroll
            for (int i = 0; i < 2; i++) {            // A tile [128][20] (m-major)
                int id = tid * 2 + i;
                int row = id >> 2, ch = (id & 3) * 4;
                cp16(&As[buf][row * 20 + ch], Ap + (size_t)(bm + row) * Kd + k0 + ch);
            }
        }
        cp_commit();
    };

    float d[4][4][4];                                // [mt][nt][frag]
    #pragma unroll
    for (int i = 0; i < 4; i++)
        #pragma unroll
        for (int j = 0; j < 4; j++)
            #pragma unroll
            for (int q = 0; q < 4; q++) d[i][j][q] = 0.0f;

    issue(0, 0);
    issue(1, 1);

    for (int t = 0; t < T; t++) {
        if (t + 1 < T) asm volatile("cp.async.wait_group 1;\n" ::);
        else           asm volatile("cp.async.wait_group 0;\n" ::);
        __syncthreads();

        const float* as = As[t & 1];
        const float* bs = Bs[t & 1];

        #pragma unroll
        for (int ks = 0; ks < 16; ks += 8) {
            // B fragments: b0 = B[ks+tg][n], b1 = B[ks+4+tg][n]
            uint32_t bhi[4][2], blo[4][2];
            #pragma unroll
            for (int nt = 0; nt < 4; nt++) {
                int n = nw + nt * 8 + g;
                float f0 = bs[(ks + tg) * BP + n];
                float f1 = bs[(ks + 4 + tg) * BP + n];
                tf32_split(f0, bhi[nt][0], blo[nt][0]);
                tf32_split(f1, bhi[nt][1], blo[nt][1]);
            }
            #pragma unroll
            for (int mt = 0; mt < 4; mt++) {
                int r0 = mw + mt * 16 + g;
                float fa0, fa1, fa2, fa3;
                if (TA) {
                    fa0 = as[(ks + tg) * 136 + r0];
                    fa1 = as[(ks + tg) * 136 + r0 + 8];
                    fa2 = as[(ks + 4 + tg) * 136 + r0];
                    fa3 = as[(ks + 4 + tg) * 136 + r0 + 8];
                } else {
                    fa0 = as[r0 * 20 + ks + tg];
                    fa1 = as[(r0 + 8) * 20 + ks + tg];
                    fa2 = as[r0 * 20 + ks + 4 + tg];
                    fa3 = as[(r0 + 8) * 20 + ks + 4 + tg];
                }
                uint32_t ahi[4], alo[4];
                tf32_split(fa0, ahi[0], alo[0]);
                tf32_split(fa1, ahi[1], alo[1]);
                tf32_split(fa2, ahi[2], alo[2]);
                tf32_split(fa3, ahi[3], alo[3]);
                #pragma unroll
                for (int nt = 0; nt < 4; nt++) {
                    mma8(d[mt][nt], ahi, bhi[nt]);
                    mma8(d[mt][nt], alo, bhi[nt]);
                    mma8(d[mt][nt], ahi, blo[nt]);
                }
            }
        }
        __syncthreads();
        if (t + 2 < T) issue(t + 2, t & 1);
    }

    // epilogue: d0,d1 -> (row g, cols 2tg,2tg+1); d2,d3 -> row g+8
    float* Cp = Cm + (size_t)bz * sC;
    #pragma unroll
    for (int mt = 0; mt < 4; mt++) {
        int r0 = bm + mw + mt * 16 + g;
        float inv0 = 1.0f, inv8 = 1.0f;
        if (rowdiv) {
            inv0 = 1.0f / rowdiv[(size_t)bz * M + r0];
            inv8 = 1.0f / rowdiv[(size_t)bz * M + r0 + 8];
        }
        #pragma unroll
        for (int nt = 0; nt < 4; nt++) {
            int c = bn + nw + nt * 8 + tg * 2;
            float2 v0, v8;
            v0.x = d[mt][nt][0]; v0.y = d[mt][nt][1];
            v8.x = d[mt][nt][2]; v8.y = d[mt][nt][3];
            if (rowdiv) { v0.x *= inv0; v0.y *= inv0; v8.x *= inv8; v8.y *= inv8; }
            if (bias) {
                float2 bb = *(const float2*)&bias[c];
                v0.x += bb.x; v0.y += bb.y; v8.x += bb.x; v8.y += bb.y;
            }
            *(float2*)&Cp[(size_t)r0 * Nn + c] = v0;
            *(float2*)&Cp[(size_t)(r0 + 8) * Nn + c] = v8;
        }
    }
}

// l2-normalize row (len 256) then relu, in place
__global__ void normrelu_kernel(float* __restrict__ p) {
    size_t row = blockIdx.x;
    float* r = p + row * HH;
    float v = r[threadIdx.x];
    __shared__ float sm[256];
    sm[threadIdx.x] = v * v; __syncthreads();
    for (int o = 128; o > 0; o >>= 1) {
        if (threadIdx.x < o) sm[threadIdx.x] += sm[threadIdx.x + o];
        __syncthreads();
    }
    float nrm = fmaxf(sqrtf(sm[0]), 1e-12f);
    r[threadIdx.x] = fmaxf(v, 0.0f) / nrm;
}

// softmax over last dim (256), in place
__global__ void softmax_kernel(float* __restrict__ s) {
    size_t row = blockIdx.x;
    float* r = s + row * CC;
    float v = r[threadIdx.x];
    __shared__ float sm[256];
    sm[threadIdx.x] = v; __syncthreads();
    for (int o = 128; o > 0; o >>= 1) {
        if (threadIdx.x < o) sm[threadIdx.x] = fmaxf(sm[threadIdx.x], sm[threadIdx.x + o]);
        __syncthreads();
    }
    float mx = sm[0]; __syncthreads();
    float e = expf(v - mx);
    sm[threadIdx.x] = e; __syncthreads();
    for (int o = 128; o > 0; o >>= 1) {
        if (threadIdx.x < o) sm[threadIdx.x] += sm[threadIdx.x + o];
        __syncthreads();
    }
    r[threadIdx.x] = e / sm[0];
}

// scores[b,c] = sum_n s[b,n,c]   grid: (8, B)
__global__ void colsum_kernel(const float* __restrict__ s) {
    int b = blockIdx.y;
    const float* base = s + ((size_t)b * NN_ + (size_t)blockIdx.x * 128) * CC;
    float acc = 0.f;
    for (int r = 0; r < 128; r++) acc += base[(size_t)r * CC + threadIdx.x];
    atomicAdd(&g_scores[b * CC + threadIdx.x], acc);
}

// thresh[b] = K-th largest of scores[b,:]
__global__ void topk_kernel() {
    int b = blockIdx.x, t = threadIdx.x;
    __shared__ float sm[256];
    sm[t] = g_scores[b * CC + t]; __syncthreads();
    float v = sm[t];
    int cnt = 0;
    for (int j = 0; j < CC; j++) {
        float w = sm[j];
        cnt += (w > v) || (w == v && j < t);
    }
    if (cnt == KTOP - 1) g_thresh[b] = v;
}

// s *= sigmoid((scores - thresh)/T), accumulate entropy   grid: (8, B)
__global__ void gate_kernel(float* __restrict__ s) {
    int b = blockIdx.y, t = threadIdx.x;
    float xg = (g_scores[b * CC + t] - g_thresh[b]) / TEMPR;
    float gt;
    if (xg >= 0.f) gt = 1.0f / (1.0f + expf(-xg));
    else { float ex = expf(xg); gt = ex / (1.0f + ex); }
    float* base = s + ((size_t)b * NN_ + (size_t)blockIdx.x * 128) * CC;
    double e = 0.0;
    for (int r = 0; r < 128; r++) {
        size_t idx = (size_t)r * CC + t;
        float v = base[idx] * gt;
        base[idx] = v;
        e += (double)(-v * logf(v + 1e-15f));
    }
    __shared__ double sm[256];
    double tot = block_red_d(e, sm);
    if (t == 0) atomicAdd(&g_ent, tot);
}

// global sum of adj^2 (double)
__global__ void sumsq_kernel(const float* __restrict__ adj, size_t n) {
    double acc = 0.0;
    for (size_t i = (size_t)blockIdx.x * blockDim.x + threadIdx.x; i < n;
         i += (size_t)gridDim.x * blockDim.x) {
        float v = adj[i];
        acc += (double)v * v;
    }
    __shared__ double sm[256];
    double tot = block_red_d(acc, sm);
    if (threadIdx.x == 0) atomicAdd(&g_sumsq_adj, tot);
}

// per-batch traces / frobenius sums over [C,C] mats
__global__ void batchred_kernel(const float* __restrict__ adjp) {
    int b = blockIdx.x, t = threadIdx.x;
    const float* P = adjp  + (size_t)b * CC * CC;
    const float* G = g_sts + (size_t)b * CC * CC;
    const float* U = g_U   + (size_t)b * CC * CC;
    const float* V = g_V   + (size_t)b * CC * CC;
    double trA = 0, ssA = 0, trG = 0, ssG = 0, duv = 0;
    for (int i = t; i < CC * CC; i += 256) {
        float p = P[i]; ssA += (double)p * p;
        float g = G[i]; ssG += (double)g * g;
        duv += (double)U[i] * (double)V[i];
        if (i % (CC + 1) == 0) { trA += p; trG += g; }
    }
    __shared__ double sm[256];
    double r;
    r = block_red_d(trA, sm); if (t == 0) g_trA[b] = r;
    r = block_red_d(ssA, sm); if (t == 0) g_ssA[b] = r;
    r = block_red_d(trG, sm); if (t == 0) g_trG[b] = r;
    r = block_red_d(ssG, sm); if (t == 0) g_ssG[b] = r;
    r = block_red_d(duv, sm); if (t == 0) g_dotUV[b] = r;
}

// final scalars: link, ent, clu, recon
__global__ void final_kernel(float* __restrict__ o) {
    double linksq = g_sumsq_adj, reconsq = g_sumsq_adj, clusum = 0.0;
    for (int b = 0; b < BB; b++) {
        linksq  += -2.0 * g_trA[b] + g_ssG[b];
        reconsq += -2.0 * g_ssA[b] + g_dotUV[b];
        double nrm = sqrt(g_ssG[b]); if (nrm < 1e-12) nrm = 1e-12;
        double t1 = g_ssG[b] / (nrm * nrm);
        double cb = t1 - 2.0 * g_trG[b] / (nrm * 16.0) + 1.0;   // sqrt(C)=16
        clusum += sqrt(cb > 0.0 ? cb : 0.0);
    }
    double sz = (double)BB * NN_ * NN_;
    o[0] = (float)(sqrt(linksq  > 0.0 ? linksq  : 0.0) / sz);  // link
    o[1] = (float)(g_ent / ((double)BB * NN_));                // ent
    o[2] = (float)(clusum / BB);                               // clu
    o[3] = (float)(sqrt(reconsq > 0.0 ? reconsq : 0.0) / sz);  // recon
}

// ---------------- launch ----------------
extern "C" void kernel_launch(void* const* d_in, const int* in_sizes, int n_in,
                              void* d_out, int out_size) {
    const float* x    = (const float*)d_in[0];
    const float* adj  = (const float*)d_in[1];
    const float* Wr_p = (const float*)d_in[2];
    const float* br_p = (const float*)d_in[3];
    const float* Wo_p = (const float*)d_in[4];
    const float* Wl_p = (const float*)d_in[5];
    const float* bl_p = (const float*)d_in[6];
    const float* Wr_e = (const float*)d_in[7];
    const float* br_e = (const float*)d_in[8];
    const float* Wo_e = (const float*)d_in[9];
    const float* Wl_e = (const float*)d_in[10];
    const float* bl_e = (const float*)d_in[11];

    float* out       = (float*)d_out;
    float* out_xp    = out;                         // [B,C,E]
    float* out_adjp  = out + 2097152;               // [B,C,C]
    float* out_s     = out + 4194304;               // [B,N,C]
    float* out_scal  = out + 12582912;              // link, ent, clu, recon
    float* out_nodex = out + 12582916;              // [B,N,E]

    float *p_deg, *p_agg, *p_pre, *p_sTa, *p_sts, *p_U, *p_V;
    cudaGetSymbolAddress((void**)&p_deg, g_deg);
    cudaGetSymbolAddress((void**)&p_agg, g_agg);
    cudaGetSymbolAddress((void**)&p_pre, g_pre);
    cudaGetSymbolAddress((void**)&p_sTa, g_sTa);
    cudaGetSymbolAddress((void**)&p_sts, g_sts);
    cudaGetSymbolAddress((void**)&p_U,   g_U);
    cudaGetSymbolAddress((void**)&p_V,   g_V);

    init_kernel<<<32, 256>>>();
    deg_kernel<<<BB * NN_, 256>>>(adj);

    // agg = (adj @ x) / deg   batched: M=1024, N=D, K=1024
    gemm128<false><<<dim3(DD / 128, NN_ / 128, BB), 256>>>(
        adj, x, p_agg, nullptr, nullptr, nullptr, p_deg,
        NN_, DD, NN_, (size_t)NN_ * NN_, (size_t)NN_ * DD, (size_t)NN_ * DD);

    // ---- embed branch: pre = agg@Wr_e + x@Wo_e + br_e (fused dual-source) ----
    gemm128<false><<<dim3(HH / 128, (BB * NN_) / 128, 1), 256>>>(
        p_agg, Wr_e, p_pre, x, Wo_e, br_e, nullptr,
        BB * NN_, HH, DD, 0, 0, 0);
    normrelu_kernel<<<BB * NN_, 256>>>(p_pre);
    gemm128<false><<<dim3(EE / 128, (BB * NN_) / 128, 1), 256>>>(
        p_pre, Wl_e, out_nodex, nullptr, nullptr, bl_e, nullptr,
        BB * NN_, EE, HH, 0, 0, 0);

    // ---- pool branch -> logits into out_s ----
    gemm128<false><<<dim3(HH / 128, (BB * NN_) / 128, 1), 256>>>(
        p_agg, Wr_p, p_pre, x, Wo_p, br_p, nullptr,
        BB * NN_, HH, DD, 0, 0, 0);
    normrelu_kernel<<<BB * NN_, 256>>>(p_pre);
    gemm128<false><<<dim3(CC / 128, (BB * NN_) / 128, 1), 256>>>(
        p_pre, Wl_p, out_s, nullptr, nullptr, bl_p, nullptr,
        BB * NN_, CC, HH, 0, 0, 0);

    // softmax, scores, top-k gate (+entropy)
    softmax_kernel<<<BB * NN_, 256>>>(out_s);
    colsum_kernel<<<dim3(8, BB), 256>>>(out_s);
    topk_kernel<<<BB, 256>>>();
    gate_kernel<<<dim3(8, BB), 256>>>(out_s);

    // xp = s^T @ node_x    TN: M=C, N=E, K=N
    gemm128<true><<<dim3(EE / 128, CC / 128, BB), 256>>>(
        out_s, out_nodex, out_xp, nullptr, nullptr, nullptr, nullptr,
        CC, EE, NN_, (size_t)NN_ * CC, (size_t)NN_ * EE, (size_t)CC * EE);

    // sTa = s^T @ adj      TN: M=C, N=N, K=N
    gemm128<true><<<dim3(NN_ / 128, CC / 128, BB), 256>>>(
        out_s, adj, p_sTa, nullptr, nullptr, nullptr, nullptr,
        CC, NN_, NN_, (size_t)NN_ * CC, (size_t)NN_ * NN_, (size_t)CC * NN_);

    // adj_p = sTa @ s      NN: M=C, N=C, K=N
    gemm128<false><<<dim3(CC / 128, CC / 128, BB), 256>>>(
        p_sTa, out_s, out_adjp, nullptr, nullptr, nullptr, nullptr,
        CC, CC, NN_, (size_t)CC * NN_, (size_t)NN_ * CC, (size_t)CC * CC);

    // sts = s^T @ s        TN: M=C, N=C, K=N
    gemm128<true><<<dim3(CC / 128, CC / 128, BB), 256>>>(
        out_s, out_s, p_sts, nullptr, nullptr, nullptr, nullptr,
        CC, CC, NN_, (size_t)NN_ * CC, (size_t)NN_ * CC, (size_t)CC * CC);

    // U = adj_p @ sts,  V = sts @ adj_p   (for ||S P S^T||^2 = <U, V>)
    gemm128<false><<<dim3(CC / 128, CC / 128, BB), 256>>>(
        out_adjp, p_sts, p_U, nullptr, nullptr, nullptr, nullptr,
        CC, CC, CC, (size_t)CC * CC, (size_t)CC * CC, (size_t)CC * CC);
    gemm128<false><<<dim3(CC / 128, CC / 128, BB), 256>>>(
        p_sts, out_adjp, p_V, nullptr, nullptr, nullptr, nullptr,
        CC, CC, CC, (size_t)CC * CC, (size_t)CC * CC, (size_t)CC * CC);

    // scalar losses
    sumsq_kernel<<<1024, 256>>>(adj, (size_t)BB * NN_ * NN_);
    batchred_kernel<<<BB, 256>>>(out_adjp);
    final_kernel<<<1, 1>>>(out_scal);
}

// round 7
// speedup vs baseline: 1.3795x; 1.3795x over previous
#include <cuda_runtime.h>
#include <math.h>
#include <stdint.h>

// Problem constants
#define BB   32
#define NN_  1024
#define DD   256
#define HH   256
#define EE   256
#define CC   256
#define KTOP 128
#define TEMPR 0.1f

// ---------------- scratch (device globals; no allocation allowed) ----------------
__device__ float g_deg[BB * NN_];
__device__ float g_agg[BB * NN_ * DD];       // 32 MB
__device__ float g_pre[BB * NN_ * HH];       // 32 MB
__device__ float g_sTa[BB * CC * NN_];       // 32 MB
__device__ float g_sts[BB * CC * CC];        // 8 MB
__device__ float g_U[BB * CC * CC];          // 8 MB
__device__ float g_V[BB * CC * CC];          // 8 MB
__device__ float g_scores[BB * CC];
__device__ float g_thresh[BB];
__device__ double g_sumsq_adj;
__device__ double g_ent;
__device__ double g_trA[BB], g_ssA[BB], g_trG[BB], g_ssG[BB], g_dotUV[BB];

// ---------------- helpers ----------------
__device__ __forceinline__ double block_red_d(double v, double* sm) {
    int t = threadIdx.x;
    sm[t] = v; __syncthreads();
    for (int o = 128; o > 0; o >>= 1) {
        if (t < o) sm[t] += sm[t + o];
        __syncthreads();
    }
    double r = sm[0]; __syncthreads();
    return r;
}

__device__ __forceinline__ void cp16(void* s, const void* g) {
    uint32_t si = (uint32_t)__cvta_generic_to_shared(s);
    asm volatile("cp.async.cg.shared.global [%0], [%1], 16;\n" :: "r"(si), "l"(g));
}
__device__ __forceinline__ void cp_commit() {
    asm volatile("cp.async.commit_group;\n" ::);
}

// tf32 hi/lo split: f = hi + lo (+ ~2^-23 f), both tf32-rounded fp32 patterns
__device__ __forceinline__ void tf32_split(float f, float& hi, float& lo) {
    uint32_t h, l;
    asm("cvt.rna.tf32.f32 %0, %1;" : "=r"(h) : "f"(f));
    float r = f - __uint_as_float(h);
    asm("cvt.rna.tf32.f32 %0, %1;" : "=r"(l) : "f"(r));
    hi = __uint_as_float(h);
    lo = __uint_as_float(l);
}

// D += A(tf32) * B(tf32), m16n8k8
__device__ __forceinline__ void mma8(float* d, const uint32_t* a, const uint32_t* b) {
    asm volatile(
        "mma.sync.aligned.m16n8k8.row.col.f32.tf32.tf32.f32 "
        "{%0,%1,%2,%3},{%4,%5,%6,%7},{%8,%9},{%0,%1,%2,%3};"
        : "+f"(d[0]), "+f"(d[1]), "+f"(d[2]), "+f"(d[3])
        : "r"(a[0]), "r"(a[1]), "r"(a[2]), "r"(a[3]), "r"(b[0]), "r"(b[1]));
}

__global__ void init_kernel() {
    int i = blockIdx.x * blockDim.x + threadIdx.x;
    if (i < BB * CC) g_scores[i] = 0.0f;
    if (i == 0) { g_sumsq_adj = 0.0; g_ent = 0.0; }
}

// degree: deg[b,n] = max(1, sum_m adj[b,n,m])
__global__ void deg_kernel(const float* __restrict__ adj) {
    int row = blockIdx.x;
    const float* a = adj + (size_t)row * NN_;
    float s = 0.f;
    for (int i = threadIdx.x; i < NN_; i += 256) s += a[i];
    __shared__ float sm[256];
    sm[threadIdx.x] = s; __syncthreads();
    for (int o = 128; o > 0; o >>= 1) {
        if (threadIdx.x < o) sm[threadIdx.x] += sm[threadIdx.x + o];
        __syncthreads();
    }
    if (threadIdx.x == 0) g_deg[row] = fmaxf(sm[0], 1.0f);
}

// ---------------- tensor-core 128x128x16 GEMM: tf32 3x, split-once-in-smem ------
// C = op(A)@B [+ op2(A2)@B2] [+bias][/rowdiv]
// TA=false: A is [M,K] row-major. TA=true: A is [K,M] row-major.
// B is [K,N] row-major. M,N multiples of 128; K multiple of 16.
// 8 warps = 2(m) x 4(n); warp tile 64x32 = 4x4 m16n8 fragments.
// Dynamic smem layout (floats):
//   rawA[2] @ 0, 2560      (TA? [16][136] : [128][20])
//   rawB[2] @ 5120, 7296   ([16][136])
//   Ahi @ 9472, Alo @ 11648, Bhi @ 13824, Blo @ 16000  ([16][136] k-major)
#define GSMEM_F 18176
#define GSMEM_B (GSMEM_F * 4)

template<bool TA>
__global__ __launch_bounds__(256, 2) void gemm128(
    const float* __restrict__ A, const float* __restrict__ Bm,
    float* __restrict__ Cm,
    const float* __restrict__ A2, const float* __restrict__ B2,
    const float* __restrict__ bias, const float* __restrict__ rowdiv,
    int M, int Nn, int Kd, size_t sA, size_t sB, size_t sC)
{
    extern __shared__ float smem[];
    float* rawA0 = smem;
    float* rawA1 = smem + 2560;
    float* rawB0 = smem + 5120;
    float* rawB1 = smem + 7296;
    float* Ahi   = smem + 9472;
    float* Alo   = smem + 11648;
    float* Bhi   = smem + 13824;
    float* Blo   = smem + 16000;

    int bz = blockIdx.z;
    int bm = blockIdx.y * 128, bn = blockIdx.x * 128;
    int tid = threadIdx.x;
    int lane = tid & 31, wid = tid >> 5;
    int g = lane >> 2, tg = lane & 3;
    int mw = (wid & 1) * 64, nw = (wid >> 1) * 32;

    const float* Ab1 = A  + (size_t)bz * sA;
    const float* Bb1 = Bm + (size_t)bz * sB;
    const float* Ab2 = A2 ? A2 + (size_t)bz * sA : nullptr;
    const float* Bb2 = A2 ? B2 + (size_t)bz * sB : nullptr;
    const int T1 = Kd / 16;
    const int T  = A2 ? 2 * T1 : T1;

    auto issue = [&](int t, int buf) {
        const float* Ap; const float* Bp; int k0;
        if (t < T1) { Ap = Ab1; Bp = Bb1; k0 = t * 16; }
        else        { Ap = Ab2; Bp = Bb2; k0 = (t - T1) * 16; }
        float* rb = buf ? rawB1 : rawB0;
        float* ra = buf ? rawA1 : rawA0;
        #pragma unroll
        for (int i = 0; i < 2; i++) {                // B [16][136]
            int id = tid * 2 + i;
            int r = id >> 5, c = (id & 31) * 4;
            cp16(&rb[r * 136 + c], Bp + (size_t)(k0 + r) * Nn + bn + c);
        }
        if (TA) {
            #pragma unroll
            for (int i = 0; i < 2; i++) {            // A [16][136] (k-major)
                int id = tid * 2 + i;
                int r = id >> 5, c = (id & 31) * 4;
                cp16(&ra[r * 136 + c], Ap + (size_t)(k0 + r) * M + bm + c);
            }
        } else {
            #pragma unroll
            for (int i = 0; i < 2; i++) {            // A [128][20] (m-major)
                int id = tid * 2 + i;
                int row = id >> 2, ch = (id & 3) * 4;
                cp16(&ra[row * 20 + ch], Ap + (size_t)(bm + row) * Kd + k0 + ch);
            }
        }
        cp_commit();
    };

    float d[4][4][4];
    #pragma unroll
    for (int i = 0; i < 4; i++)
        #pragma unroll
        for (int j = 0; j < 4; j++)
            #pragma unroll
            for (int q = 0; q < 4; q++) d[i][j][q] = 0.0f;

    issue(0, 0);
    issue(1, 1);

    for (int t = 0; t < T; t++) {
        if (t + 1 < T) asm volatile("cp.async.wait_group 1;\n" ::);
        else           asm volatile("cp.async.wait_group 0;\n" ::);
        __syncthreads();   // raw[t] arrived; previous MMA (conv readers) done

        float* ra = (t & 1) ? rawA1 : rawA0;
        float* rb = (t & 1) ? rawB1 : rawB0;

        // ---- convert phase: split raw fp32 -> hi/lo tf32 planes (once per element)
        {   // B: 16x128, 8 elems/thread, vectorized
            int k = tid >> 4, n = (tid & 15) * 8;
            int o = k * 136 + n;
            float4 v0 = *(const float4*)&rb[o];
            float4 v1 = *(const float4*)&rb[o + 4];
            float4 h0, l0, h1, l1;
            tf32_split(v0.x, h0.x, l0.x); tf32_split(v0.y, h0.y, l0.y);
            tf32_split(v0.z, h0.z, l0.z); tf32_split(v0.w, h0.w, l0.w);
            tf32_split(v1.x, h1.x, l1.x); tf32_split(v1.y, h1.y, l1.y);
            tf32_split(v1.z, h1.z, l1.z); tf32_split(v1.w, h1.w, l1.w);
            *(float4*)&Bhi[o] = h0; *(float4*)&Bhi[o + 4] = h1;
            *(float4*)&Blo[o] = l0; *(float4*)&Blo[o + 4] = l1;
        }
        if (TA) {           // A raw already k-major [16][136]
            int k = tid >> 4, n = (tid & 15) * 8;
            int o = k * 136 + n;
            float4 v0 = *(const float4*)&ra[o];
            float4 v1 = *(const float4*)&ra[o + 4];
            float4 h0, l0, h1, l1;
            tf32_split(v0.x, h0.x, l0.x); tf32_split(v0.y, h0.y, l0.y);
            tf32_split(v0.z, h0.z, l0.z); tf32_split(v0.w, h0.w, l0.w);
            tf32_split(v1.x, h1.x, l1.x); tf32_split(v1.y, h1.y, l1.y);
            tf32_split(v1.z, h1.z, l1.z); tf32_split(v1.w, h1.w, l1.w);
            *(float4*)&Ahi[o] = h0; *(float4*)&Ahi[o + 4] = h1;
            *(float4*)&Alo[o] = l0; *(float4*)&Alo[o + 4] = l1;
        } else {            // A raw [128][20] m-major -> transpose into [16][136]
            int m = tid >> 1, kb = (tid & 1) * 8;
            int o = m * 20 + kb;
            float4 v0 = *(const float4*)&ra[o];
            float4 v1 = *(const float4*)&ra[o + 4];
            float f[8] = {v0.x, v0.y, v0.z, v0.w, v1.x, v1.y, v1.z, v1.w};
            #pragma unroll
            for (int j = 0; j < 8; j++) {
                float h, l;
                tf32_split(f[j], h, l);
                Ahi[(kb + j) * 136 + m] = h;
                Alo[(kb + j) * 136 + m] = l;
            }
        }
        __syncthreads();    // conv planes ready; raw[t] free
        if (t + 2 < T) issue(t + 2, t & 1);

        // ---- MMA phase: pure LDS + HMMA, conflict-free
        #pragma unroll
        for (int ks = 0; ks < 16; ks += 8) {
            int kro = (ks + tg) * 136;
            uint32_t bh[4][2], bl[4][2];
            #pragma unroll
            for (int nt = 0; nt < 4; nt++) {
                int o = kro + nw + nt * 8 + g;
                bh[nt][0] = __float_as_uint(Bhi[o]);
                bh[nt][1] = __float_as_uint(Bhi[o + 544]);
                bl[nt][0] = __float_as_uint(Blo[o]);
                bl[nt][1] = __float_as_uint(Blo[o + 544]);
            }
            #pragma unroll
            for (int mt = 0; mt < 4; mt++) {
                int o = kro + mw + mt * 16 + g;
                uint32_t ah[4], al[4];
                ah[0] = __float_as_uint(Ahi[o]);
                ah[1] = __float_as_uint(Ahi[o + 8]);
                ah[2] = __float_as_uint(Ahi[o + 544]);
                ah[3] = __float_as_uint(Ahi[o + 552]);
                al[0] = __float_as_uint(Alo[o]);
                al[1] = __float_as_uint(Alo[o + 8]);
                al[2] = __float_as_uint(Alo[o + 544]);
                al[3] = __float_as_uint(Alo[o + 552]);
                #pragma unroll
                for (int nt = 0; nt < 4; nt++) {
                    mma8(d[mt][nt], ah, bh[nt]);
                    mma8(d[mt][nt], al, bh[nt]);
                    mma8(d[mt][nt], ah, bl[nt]);
                }
            }
        }
        // no sync needed here: next iteration's first sync protects conv planes
    }

    // epilogue: d0,d1 -> (row g, cols 2tg,2tg+1); d2,d3 -> row g+8
    float* Cp = Cm + (size_t)bz * sC;
    #pragma unroll
    for (int mt = 0; mt < 4; mt++) {
        int r0 = bm + mw + mt * 16 + g;
        float inv0 = 1.0f, inv8 = 1.0f;
        if (rowdiv) {
            inv0 = 1.0f / rowdiv[(size_t)bz * M + r0];
            inv8 = 1.0f / rowdiv[(size_t)bz * M + r0 + 8];
        }
        #pragma unroll
        for (int nt = 0; nt < 4; nt++) {
            int c = bn + nw + nt * 8 + tg * 2;
            float2 v0, v8;
            v0.x = d[mt][nt][0]; v0.y = d[mt][nt][1];
            v8.x = d[mt][nt][2]; v8.y = d[mt][nt][3];
            if (rowdiv) { v0.x *= inv0; v0.y *= inv0; v8.x *= inv8; v8.y *= inv8; }
            if (bias) {
                float2 bb = *(const float2*)&bias[c];
                v0.x += bb.x; v0.y += bb.y; v8.x += bb.x; v8.y += bb.y;
            }
            *(float2*)&Cp[(size_t)r0 * Nn + c] = v0;
            *(float2*)&Cp[(size_t)(r0 + 8) * Nn + c] = v8;
        }
    }
}

// l2-normalize row (len 256) then relu, in place
__global__ void normrelu_kernel(float* __restrict__ p) {
    size_t row = blockIdx.x;
    float* r = p + row * HH;
    float v = r[threadIdx.x];
    __shared__ float sm[256];
    sm[threadIdx.x] = v * v; __syncthreads();
    for (int o = 128; o > 0; o >>= 1) {
        if (threadIdx.x < o) sm[threadIdx.x] += sm[threadIdx.x + o];
        __syncthreads();
    }
    float nrm = fmaxf(sqrtf(sm[0]), 1e-12f);
    r[threadIdx.x] = fmaxf(v, 0.0f) / nrm;
}

// softmax over last dim (256), in place
__global__ void softmax_kernel(float* __restrict__ s) {
    size_t row = blockIdx.x;
    float* r = s + row * CC;
    float v = r[threadIdx.x];
    __shared__ float sm[256];
    sm[threadIdx.x] = v; __syncthreads();
    for (int o = 128; o > 0; o >>= 1) {
        if (threadIdx.x < o) sm[threadIdx.x] = fmaxf(sm[threadIdx.x], sm[threadIdx.x + o]);
        __syncthreads();
    }
    float mx = sm[0]; __syncthreads();
    float e = expf(v - mx);
    sm[threadIdx.x] = e; __syncthreads();
    for (int o = 128; o > 0; o >>= 1) {
        if (threadIdx.x < o) sm[threadIdx.x] += sm[threadIdx.x + o];
        __syncthreads();
    }
    r[threadIdx.x] = e / sm[0];
}

// scores[b,c] = sum_n s[b,n,c]   grid: (8, B)
__global__ void colsum_kernel(const float* __restrict__ s) {
    int b = blockIdx.y;
    const float* base = s + ((size_t)b * NN_ + (size_t)blockIdx.x * 128) * CC;
    float acc = 0.f;
    for (int r = 0; r < 128; r++) acc += base[(size_t)r * CC + threadIdx.x];
    atomicAdd(&g_scores[b * CC + threadIdx.x], acc);
}

// thresh[b] = K-th largest of scores[b,:]
__global__ void topk_kernel() {
    int b = blockIdx.x, t = threadIdx.x;
    __shared__ float sm[256];
    sm[t] = g_scores[b * CC + t]; __syncthreads();
    float v = sm[t];
    int cnt = 0;
    for (int j = 0; j < CC; j++) {
        float w = sm[j];
        cnt += (w > v) || (w == v && j < t);
    }
    if (cnt == KTOP - 1) g_thresh[b] = v;
}

// s *= sigmoid((scores - thresh)/T), accumulate entropy   grid: (8, B)
__global__ void gate_kernel(float* __restrict__ s) {
    int b = blockIdx.y, t = threadIdx.x;
    float xg = (g_scores[b * CC + t] - g_thresh[b]) / TEMPR;
    float gt;
    if (xg >= 0.f) gt = 1.0f / (1.0f + expf(-xg));
    else { float ex = expf(xg); gt = ex / (1.0f + ex); }
    float* base = s + ((size_t)b * NN_ + (size_t)blockIdx.x * 128) * CC;
    double e = 0.0;
    for (int r = 0; r < 128; r++) {
        size_t idx = (size_t)r * CC + t;
        float v = base[idx] * gt;
        base[idx] = v;
        e += (double)(-v * logf(v + 1e-15f));
    }
    __shared__ double sm[256];
    double tot = block_red_d(e, sm);
    if (t == 0) atomicAdd(&g_ent, tot);
}

// global sum of adj^2 (double)
__global__ void sumsq_kernel(const float* __restrict__ adj, size_t n) {
    double acc = 0.0;
    for (size_t i = (size_t)blockIdx.x * blockDim.x + threadIdx.x; i < n;
         i += (size_t)gridDim.x * blockDim.x) {
        float v = adj[i];
        acc += (double)v * v;
    }
    __shared__ double sm[256];
    double tot = block_red_d(acc, sm);
    if (threadIdx.x == 0) atomicAdd(&g_sumsq_adj, tot);
}

// per-batch traces / frobenius sums over [C,C] mats
__global__ void batchred_kernel(const float* __restrict__ adjp) {
    int b = blockIdx.x, t = threadIdx.x;
    const float* P = adjp  + (size_t)b * CC * CC;
    const float* G = g_sts + (size_t)b * CC * CC;
    const float* U = g_U   + (size_t)b * CC * CC;
    const float* V = g_V   + (size_t)b * CC * CC;
    double trA = 0, ssA = 0, trG = 0, ssG = 0, duv = 0;
    for (int i = t; i < CC * CC; i += 256) {
        float p = P[i]; ssA += (double)p * p;
        float g = G[i]; ssG += (double)g * g;
        duv += (double)U[i] * (double)V[i];
        if (i % (CC + 1) == 0) { trA += p; trG += g; }
    }
    __shared__ double sm[256];
    double r;
    r = block_red_d(trA, sm); if (t == 0) g_trA[b] = r;
    r = block_red_d(ssA, sm); if (t == 0) g_ssA[b] = r;
    r = block_red_d(trG, sm); if (t == 0) g_trG[b] = r;
    r = block_red_d(ssG, sm); if (t == 0) g_ssG[b] = r;
    r = block_red_d(duv, sm); if (t == 0) g_dotUV[b] = r;
}

// final scalars: link, ent, clu, recon
__global__ void final_kernel(float* __restrict__ o) {
    double linksq = g_sumsq_adj, reconsq = g_sumsq_adj, clusum = 0.0;
    for (int b = 0; b < BB; b++) {
        linksq  += -2.0 * g_trA[b] + g_ssG[b];
        reconsq += -2.0 * g_ssA[b] + g_dotUV[b];
        double nrm = sqrt(g_ssG[b]); if (nrm < 1e-12) nrm = 1e-12;
        double t1 = g_ssG[b] / (nrm * nrm);
        double cb = t1 - 2.0 * g_trG[b] / (nrm * 16.0) + 1.0;   // sqrt(C)=16
        clusum += sqrt(cb > 0.0 ? cb : 0.0);
    }
    double sz = (double)BB * NN_ * NN_;
    o[0] = (float)(sqrt(linksq  > 0.0 ? linksq  : 0.0) / sz);  // link
    o[1] = (float)(g_ent / ((double)BB * NN_));                // ent
    o[2] = (float)(clusum / BB);                               // clu
    o[3] = (float)(sqrt(reconsq > 0.0 ? reconsq : 0.0) / sz);  // recon
}

// ---------------- launch ----------------
extern "C" void kernel_launch(void* const* d_in, const int* in_sizes, int n_in,
                              void* d_out, int out_size) {
    const float* x    = (const float*)d_in[0];
    const float* adj  = (const float*)d_in[1];
    const float* Wr_p = (const float*)d_in[2];
    const float* br_p = (const float*)d_in[3];
    const float* Wo_p = (const float*)d_in[4];
    const float* Wl_p = (const float*)d_in[5];
    const float* bl_p = (const float*)d_in[6];
    const float* Wr_e = (const float*)d_in[7];
    const float* br_e = (const float*)d_in[8];
    const float* Wo_e = (const float*)d_in[9];
    const float* Wl_e = (const float*)d_in[10];
    const float* bl_e = (const float*)d_in[11];

    float* out       = (float*)d_out;
    float* out_xp    = out;                         // [B,C,E]
    float* out_adjp  = out + 2097152;               // [B,C,C]
    float* out_s     = out + 4194304;               // [B,N,C]
    float* out_scal  = out + 12582912;              // link, ent, clu, recon
    float* out_nodex = out + 12582916;              // [B,N,E]

    float *p_deg, *p_agg, *p_pre, *p_sTa, *p_sts, *p_U, *p_V;
    cudaGetSymbolAddress((void**)&p_deg, g_deg);
    cudaGetSymbolAddress((void**)&p_agg, g_agg);
    cudaGetSymbolAddress((void**)&p_pre, g_pre);
    cudaGetSymbolAddress((void**)&p_sTa, g_sTa);
    cudaGetSymbolAddress((void**)&p_sts, g_sts);
    cudaGetSymbolAddress((void**)&p_U,   g_U);
    cudaGetSymbolAddress((void**)&p_V,   g_V);

    cudaFuncSetAttribute(gemm128<false>,
                         cudaFuncAttributeMaxDynamicSharedMemorySize, GSMEM_B);
    cudaFuncSetAttribute(gemm128<true>,
                         cudaFuncAttributeMaxDynamicSharedMemorySize, GSMEM_B);

    init_kernel<<<32, 256>>>();
    deg_kernel<<<BB * NN_, 256>>>(adj);

    // agg = (adj @ x) / deg   batched: M=1024, N=D, K=1024
    gemm128<false><<<dim3(DD / 128, NN_ / 128, BB), 256, GSMEM_B>>>(
        adj, x, p_agg, nullptr, nullptr, nullptr, p_deg,
        NN_, DD, NN_, (size_t)NN_ * NN_, (size_t)NN_ * DD, (size_t)NN_ * DD);

    // ---- embed branch: pre = agg@Wr_e + x@Wo_e + br_e (fused dual-source) ----
    gemm128<false><<<dim3(HH / 128, (BB * NN_) / 128, 1), 256, GSMEM_B>>>(
        p_agg, Wr_e, p_pre, x, Wo_e, br_e, nullptr,
        BB * NN_, HH, DD, 0, 0, 0);
    normrelu_kernel<<<BB * NN_, 256>>>(p_pre);
    gemm128<false><<<dim3(EE / 128, (BB * NN_) / 128, 1), 256, GSMEM_B>>>(
        p_pre, Wl_e, out_nodex, nullptr, nullptr, bl_e, nullptr,
        BB * NN_, EE, HH, 0, 0, 0);

    // ---- pool branch -> logits into out_s ----
    gemm128<false><<<dim3(HH / 128, (BB * NN_) / 128, 1), 256, GSMEM_B>>>(
        p_agg, Wr_p, p_pre, x, Wo_p, br_p, nullptr,
        BB * NN_, HH, DD, 0, 0, 0);
    normrelu_kernel<<<BB * NN_, 256>>>(p_pre);
    gemm128<false><<<dim3(CC / 128, (BB * NN_) / 128, 1), 256, GSMEM_B>>>(
        p_pre, Wl_p, out_s, nullptr, nullptr, bl_p, nullptr,
        BB * NN_, CC, HH, 0, 0, 0);

    // softmax, scores, top-k gate (+entropy)
    softmax_kernel<<<BB * NN_, 256>>>(out_s);
    colsum_kernel<<<dim3(8, BB), 256>>>(out_s);
    topk_kernel<<<BB, 256>>>();
    gate_kernel<<<dim3(8, BB), 256>>>(out_s);

    // xp = s^T @ node_x    TN: M=C, N=E, K=N
    gemm128<true><<<dim3(EE / 128, CC / 128, BB), 256, GSMEM_B>>>(
        out_s, out_nodex, out_xp, nullptr, nullptr, nullptr, nullptr,
        CC, EE, NN_, (size_t)NN_ * CC, (size_t)NN_ * EE, (size_t)CC * EE);

    // sTa = s^T @ adj      TN: M=C, N=N, K=N
    gemm128<true><<<dim3(NN_ / 128, CC / 128, BB), 256, GSMEM_B>>>(
        out_s, adj, p_sTa, nullptr, nullptr, nullptr, nullptr,
        CC, NN_, NN_, (size_t)NN_ * CC, (size_t)NN_ * NN_, (size_t)CC * NN_);

    // adj_p = sTa @ s      NN: M=C, N=C, K=N
    gemm128<false><<<dim3(CC / 128, CC / 128, BB), 256, GSMEM_B>>>(
        p_sTa, out_s, out_adjp, nullptr, nullptr, nullptr, nullptr,
        CC, CC, NN_, (size_t)CC * NN_, (size_t)NN_ * CC, (size_t)CC * CC);

    // sts = s^T @ s        TN: M=C, N=C, K=N
    gemm128<true><<<dim3(CC / 128, CC / 128, BB), 256, GSMEM_B>>>(
        out_s, out_s, p_sts, nullptr, nullptr, nullptr, nullptr,
        CC, CC, NN_, (size_t)NN_ * CC, (size_t)NN_ * CC, (size_t)CC * CC);

    // U = adj_p @ sts,  V = sts @ adj_p   (for ||S P S^T||^2 = <U, V>)
    gemm128<false><<<dim3(CC / 128, CC / 128, BB), 256, GSMEM_B>>>(
        out_adjp, p_sts, p_U, nullptr, nullptr, nullptr, nullptr,
        CC, CC, CC, (size_t)CC * CC, (size_t)CC * CC, (size_t)CC * CC);
    gemm128<false><<<dim3(CC / 128, CC / 128, BB), 256, GSMEM_B>>>(
        p_sts, out_adjp, p_V, nullptr, nullptr, nullptr, nullptr,
        CC, CC, CC, (size_t)CC * CC, (size_t)CC * CC, (size_t)CC * CC);

    // scalar losses
    sumsq_kernel<<<1024, 256>>>(adj, (size_t)BB * NN_ * NN_);
    batchred_kernel<<<BB, 256>>>(out_adjp);
    final_kernel<<<1, 1>>>(out_scal);
}

// round 8
// speedup vs baseline: 1.4801x; 1.0729x over previous
#include <cuda_runtime.h>
#include <math.h>
#include <stdint.h>

// Problem constants
#define BB   32
#define NN_  1024
#define DD   256
#define HH   256
#define EE   256
#define CC   256
#define KTOP 128
#define TEMPR 0.1f

// ---------------- scratch (device globals; no allocation allowed) ----------------
// tf32 hi/lo operand planes (k-major where used as GEMM operands)
__device__ float g_adjN_hi[33554432], g_adjN_lo[33554432];   // [b][n][m] natural
__device__ float g_adjT_hi[33554432], g_adjT_lo[33554432];   // [b][m][n] transposed
__device__ float g_xN_hi[8388608],   g_xN_lo[8388608];       // [b][m][d] natural
__device__ float g_xT_hi[8388608],   g_xT_lo[8388608];       // [b][d][m]
__device__ float g_aggT_hi[8388608], g_aggT_lo[8388608];     // [b][d][n]
__device__ float g_hT_hi[8388608],   g_hT_lo[8388608];       // [h][node_global]
__device__ float g_ndx_hi[8388608],  g_ndx_lo[8388608];      // [node][e] natural
__device__ float g_sN_hi[8388608],   g_sN_lo[8388608];       // [b][n][c] natural
__device__ float g_aTs_hi[8388608],  g_aTs_lo[8388608];      // [b][m][c] natural
__device__ float g_W_hi[6 * 65536],  g_W_lo[6 * 65536];      // 0Wr_p 1Wo_p 2Wl_p 3Wr_e 4Wo_e 5Wl_e
__device__ float g_adjpN_hi[2097152], g_adjpN_lo[2097152];
__device__ float g_adjpT_hi[2097152], g_adjpT_lo[2097152];
__device__ float g_stsN_hi[2097152],  g_stsN_lo[2097152];
__device__ float g_pre[8388608];
__device__ float g_sts[2097152], g_U[2097152], g_V[2097152];
__device__ float g_degsum[BB * NN_], g_invdeg[BB * NN_];
__device__ float g_scores[BB * CC];
__device__ float g_thresh[BB];
__device__ double g_sumsq_adj;
__device__ double g_ent;
__device__ double g_trA[BB], g_ssA[BB], g_trG[BB], g_ssG[BB], g_dotUV[BB];

// ---------------- helpers ----------------
__device__ __forceinline__ double block_red_d(double v, double* sm) {
    int t = threadIdx.x;
    sm[t] = v; __syncthreads();
    for (int o = 128; o > 0; o >>= 1) {
        if (t < o) sm[t] += sm[t + o];
        __syncthreads();
    }
    double r = sm[0]; __syncthreads();
    return r;
}

__device__ __forceinline__ void cp16(void* s, const void* g) {
    uint32_t si = (uint32_t)__cvta_generic_to_shared(s);
    asm volatile("cp.async.cg.shared.global [%0], [%1], 16;\n" :: "r"(si), "l"(g));
}
__device__ __forceinline__ void cp_commit() {
    asm volatile("cp.async.commit_group;\n" ::);
}

// tf32 hi/lo split: f = hi + lo (+ ~2^-23 f)
__device__ __forceinline__ void tf32_split(float f, float& hi, float& lo) {
    uint32_t h, l;
    asm("cvt.rna.tf32.f32 %0, %1;" : "=r"(h) : "f"(f));
    float r = f - __uint_as_float(h);
    asm("cvt.rna.tf32.f32 %0, %1;" : "=r"(l) : "f"(r));
    hi = __uint_as_float(h);
    lo = __uint_as_float(l);
}

__device__ __forceinline__ void mma8(float* d, const uint32_t* a, const uint32_t* b) {
    asm volatile(
        "mma.sync.aligned.m16n8k8.row.col.f32.tf32.tf32.f32 "
        "{%0,%1,%2,%3},{%4,%5,%6,%7},{%8,%9},{%0,%1,%2,%3};"
        : "+f"(d[0]), "+f"(d[1]), "+f"(d[2]), "+f"(d[3])
        : "r"(a[0]), "r"(a[1]), "r"(a[2]), "r"(a[3]), "r"(b[0]), "r"(b[1]));
}

__global__ void init_kernel() {
    int i = blockIdx.x * blockDim.x + threadIdx.x;
    if (i < BB * NN_) g_degsum[i] = 0.0f;
    if (i < BB * CC)  g_scores[i] = 0.0f;
    if (i == 0) { g_sumsq_adj = 0.0; g_ent = 0.0; }
}

// natural elementwise split (float4 grid-stride)
__global__ void nsplit_kernel(const float* __restrict__ in,
                              float* __restrict__ hi, float* __restrict__ lo, int n4) {
    for (int i = blockIdx.x * blockDim.x + threadIdx.x; i < n4;
         i += gridDim.x * blockDim.x) {
        float4 v = ((const float4*)in)[i];
        float4 h, l;
        tf32_split(v.x, h.x, l.x); tf32_split(v.y, h.y, l.y);
        tf32_split(v.z, h.z, l.z); tf32_split(v.w, h.w, l.w);
        ((float4*)hi)[i] = h;
        ((float4*)lo)[i] = l;
    }
}

// batched transpose-split: in [bz][M][K] -> hi/lo [bz][K][M]
__global__ void tsplit_kernel(const float* __restrict__ in,
                              float* __restrict__ hi, float* __restrict__ lo,
                              int M, int K) {
    __shared__ float sm[32][33];
    int bz = blockIdx.z;
    int k0 = blockIdx.x * 32, m0 = blockIdx.y * 32;
    int t = threadIdx.x, r = t >> 5, c = t & 31;
    const float* ip = in + (size_t)bz * M * K;
    #pragma unroll
    for (int j = 0; j < 4; j++)
        sm[r + 8 * j][c] = ip[(size_t)(m0 + r + 8 * j) * K + k0 + c];
    __syncthreads();
    size_t ob = (size_t)bz * M * K;
    #pragma unroll
    for (int j = 0; j < 4; j++) {
        int kr = r + 8 * j;
        float v = sm[c][kr];
        float h, l;
        tf32_split(v, h, l);
        size_t o = ob + (size_t)(k0 + kr) * M + m0 + c;
        hi[o] = h; lo[o] = l;
    }
}

// adj mega-pass: natural split + transposed split + deg row-sums + sumsq, one read
__global__ void split_adj_kernel(const float* __restrict__ adj) {
    __shared__ float sm[32][33];
    __shared__ double smd[256];
    int b = blockIdx.z;
    int n0 = blockIdx.y * 32, m0 = blockIdx.x * 32;
    int t = threadIdx.x, r = t >> 5, c = t & 31;
    size_t base = (size_t)b * NN_ * NN_;
    float ss = 0.f;
    #pragma unroll
    for (int j = 0; j < 4; j++) {
        int n = n0 + r + 8 * j;
        size_t o = base + (size_t)n * NN_ + m0 + c;
        float v = adj[o];
        sm[r + 8 * j][c] = v;
        ss += v * v;
        float h, l;
        tf32_split(v, h, l);
        g_adjN_hi[o] = h; g_adjN_lo[o] = l;
        float rs = v;
        #pragma unroll
        for (int w = 16; w; w >>= 1) rs += __shfl_xor_sync(0xffffffffu, rs, w);
        if (c == 0) atomicAdd(&g_degsum[b * NN_ + n], rs);
    }
    __syncthreads();
    #pragma unroll
    for (int j = 0; j < 4; j++) {
        int rr = r + 8 * j;
        float v = sm[c][rr];
        float h, l;
        tf32_split(v, h, l);
        size_t o = base + (size_t)(m0 + rr) * NN_ + n0 + c;
        g_adjT_hi[o] = h; g_adjT_lo[o] = l;
    }
    double tot = block_red_d((double)ss, smd);
    if (t == 0) atomicAdd(&g_sumsq_adj, tot);
}

__global__ void invdeg_kernel() {
    int i = blockIdx.x * blockDim.x + threadIdx.x;
    if (i < BB * NN_) g_invdeg[i] = 1.0f / fmaxf(g_degsum[i], 1.0f);
}

// ---------------- pure-plane tensor-core GEMM (128x128x16, tf32 3x) -------------
// All operands are pre-split k-major hi/lo planes. Per tile: cp.async 4 planes,
// sync, 96 LDS + 96 HMMA, sync. 8 warps = 2(m) x 4(n); warp tile 64x32.
#define GSMEM_B (17408 * 4)

__global__ __launch_bounds__(256, 2) void gemm_tc(
    const float* __restrict__ Ahi, const float* __restrict__ Alo,
    const float* __restrict__ Bhi, const float* __restrict__ Blo,
    const float* __restrict__ A2hi, const float* __restrict__ A2lo,
    const float* __restrict__ B2hi, const float* __restrict__ B2lo,
    float* __restrict__ C, float* __restrict__ Chi, float* __restrict__ Clo,
    const float* __restrict__ bias, const float* __restrict__ colmul,
    int ldA, int ldB, int Nn, int Kd,
    size_t sA, size_t sB, size_t sC, size_t sCm)
{
    extern __shared__ float smem[];   // [2][4][2176]
    int bz = blockIdx.z;
    int bm = blockIdx.y * 128, bn = blockIdx.x * 128;
    int tid = threadIdx.x;
    int lane = tid & 31, wid = tid >> 5;
    int g = lane >> 2, tg = lane & 3;
    int mw = (wid & 1) * 64, nw = (wid >> 1) * 32;

    const float* A1h = Ahi + (size_t)bz * sA;
    const float* A1l = Alo + (size_t)bz * sA;
    const float* B1h = Bhi + (size_t)bz * sB;
    const float* B1l = Blo + (size_t)bz * sB;
    const float* A2h = A2hi ? A2hi + (size_t)bz * sA : nullptr;
    const float* A2l = A2hi ? A2lo + (size_t)bz * sA : nullptr;
    const float* B2h = A2hi ? B2hi + (size_t)bz * sB : nullptr;
    const float* B2l = A2hi ? B2lo + (size_t)bz * sB : nullptr;
    const int T1 = Kd / 16;
    const int T  = A2hi ? 2 * T1 : T1;

    auto issue = [&](int t, int buf) {
        const float *ah, *al, *bh, *bl; int k0;
        if (t < T1) { ah = A1h; al = A1l; bh = B1h; bl = B1l; k0 = t * 16; }
        else        { ah = A2h; al = A2l; bh = B2h; bl = B2l; k0 = (t - T1) * 16; }
        float* S = smem + buf * 8704;
        #pragma unroll
        for (int i = 0; i < 2; i++) {
            int id = tid * 2 + i;
            int r = id >> 5, c = (id & 31) * 4;
            size_t ga = (size_t)(k0 + r) * ldA + bm + c;
            size_t gb = (size_t)(k0 + r) * ldB + bn + c;
            int so = r * 136 + c;
            cp16(&S[so],        ah + ga);
            cp16(&S[2176 + so], al + ga);
            cp16(&S[4352 + so], bh + gb);
            cp16(&S[6528 + so], bl + gb);
        }
        cp_commit();
    };

    float d[4][4][4];
    #pragma unroll
    for (int i = 0; i < 4; i++)
        #pragma unroll
        for (int j = 0; j < 4; j++)
            #pragma unroll
            for (int q = 0; q < 4; q++) d[i][j][q] = 0.0f;

    issue(0, 0);
    issue(1, 1);

    for (int t = 0; t < T; t++) {
        if (t + 1 < T) asm volatile("cp.async.wait_group 1;\n" ::);
        else           asm volatile("cp.async.wait_group 0;\n" ::);
        __syncthreads();

        const float* S   = smem + (t & 1) * 8704;
        const float* Ah  = S;
        const float* Al  = S + 2176;
        const float* Bh  = S + 4352;
        const float* Bl  = S + 6528;

        #pragma unroll
        for (int ks = 0; ks < 16; ks += 8) {
            int kro = (ks + tg) * 136;
            uint32_t bh[4][2], bl4[4][2];
            #pragma unroll
            for (int nt = 0; nt < 4; nt++) {
                int o = kro + nw + nt * 8 + g;
                bh[nt][0]  = __float_as_uint(Bh[o]);
                bh[nt][1]  = __float_as_uint(Bh[o + 544]);
                bl4[nt][0] = __float_as_uint(Bl[o]);
                bl4[nt][1] = __float_as_uint(Bl[o + 544]);
            }
            #pragma unroll
            for (int mt = 0; mt < 4; mt++) {
                int o = kro + mw + mt * 16 + g;
                uint32_t ah[4], al4[4];
                ah[0]  = __float_as_uint(Ah[o]);
                ah[1]  = __float_as_uint(Ah[o + 8]);
                ah[2]  = __float_as_uint(Ah[o + 544]);
                ah[3]  = __float_as_uint(Ah[o + 552]);
                al4[0] = __float_as_uint(Al[o]);
                al4[1] = __float_as_uint(Al[o + 8]);
                al4[2] = __float_as_uint(Al[o + 544]);
                al4[3] = __float_as_uint(Al[o + 552]);
                #pragma unroll
                for (int nt = 0; nt < 4; nt++) {
                    mma8(d[mt][nt], ah, bh[nt]);
                    mma8(d[mt][nt], al4, bh[nt]);
                    mma8(d[mt][nt], ah, bl4[nt]);
                }
            }
        }
        __syncthreads();
        if (t + 2 < T) issue(t + 2, t & 1);
    }

    // epilogue: optional colmul, bias, fp32 C, hi/lo plane outputs (natural)
    #pragma unroll
    for (int mt = 0; mt < 4; mt++) {
        int r0 = bm + mw + mt * 16 + g;
        #pragma unroll
        for (int nt = 0; nt < 4; nt++) {
            int c = bn + nw + nt * 8 + tg * 2;
            float2 v0, v8;
            v0.x = d[mt][nt][0]; v0.y = d[mt][nt][1];
            v8.x = d[mt][nt][2]; v8.y = d[mt][nt][3];
            if (colmul) {
                float cm0 = colmul[bz * sCm + c];
                float cm1 = colmul[bz * sCm + c + 1];
                v0.x *= cm0; v0.y *= cm1; v8.x *= cm0; v8.y *= cm1;
            }
            if (bias) {
                float2 bb = *(const float2*)&bias[c];
                v0.x += bb.x; v0.y += bb.y; v8.x += bb.x; v8.y += bb.y;
            }
            size_t o0 = (size_t)bz * sC + (size_t)r0 * Nn + c;
            size_t o8 = o0 + (size_t)8 * Nn;
            if (C) {
                *(float2*)&C[o0] = v0;
                *(float2*)&C[o8] = v8;
            }
            if (Chi) {
                float2 h0, l0, h8, l8;
                tf32_split(v0.x, h0.x, l0.x); tf32_split(v0.y, h0.y, l0.y);
                tf32_split(v8.x, h8.x, l8.x); tf32_split(v8.y, h8.y, l8.y);
                *(float2*)&Chi[o0] = h0; *(float2*)&Clo[o0] = l0;
                *(float2*)&Chi[o8] = h8; *(float2*)&Clo[o8] = l8;
            }
        }
    }
}

// normrelu + transpose + split: pre [32768][256] -> hT hi/lo [256][32768]
__global__ void normrelu_t_kernel() {
    __shared__ float raw[32 * 257];
    __shared__ float rnorm[32];
    int m0 = blockIdx.x * 32;
    int t = threadIdx.x, w = t >> 5, l = t & 31;
    #pragma unroll
    for (int jr = 0; jr < 4; jr++) {
        int r = w + 8 * jr;
        const float* rp = g_pre + (size_t)(m0 + r) * 256;
        float acc = 0.f;
        #pragma unroll
        for (int j = 0; j < 8; j++) {
            float v = rp[l + 32 * j];
            raw[r * 257 + l + 32 * j] = v;
            acc += v * v;
        }
        #pragma unroll
        for (int o = 16; o; o >>= 1) acc += __shfl_xor_sync(0xffffffffu, acc, o);
        if (l == 0) rnorm[r] = 1.0f / fmaxf(sqrtf(acc), 1e-12f);
    }
    __syncthreads();
    int c = t & 31, kg = t >> 5;
    float rn = rnorm[c];
    #pragma unroll
    for (int kk = 0; kk < 32; kk++) {
        int k = kg * 32 + kk;
        float v = fmaxf(raw[c * 257 + k], 0.0f) * rn;
        float h, lo_;
        tf32_split(v, h, lo_);
        size_t o = (size_t)k * 32768 + m0 + c;
        g_hT_hi[o] = h; g_hT_lo[o] = lo_;
    }
}

// softmax over last dim (256), in place
__global__ void softmax_kernel(float* __restrict__ s) {
    size_t row = blockIdx.x;
    float* r = s + row * CC;
    float v = r[threadIdx.x];
    __shared__ float sm[256];
    sm[threadIdx.x] = v; __syncthreads();
    for (int o = 128; o > 0; o >>= 1) {
        if (threadIdx.x < o) sm[threadIdx.x] = fmaxf(sm[threadIdx.x], sm[threadIdx.x + o]);
        __syncthreads();
    }
    float mx = sm[0]; __syncthreads();
    float e = expf(v - mx);
    sm[threadIdx.x] = e; __syncthreads();
    for (int o = 128; o > 0; o >>= 1) {
        if (threadIdx.x < o) sm[threadIdx.x] += sm[threadIdx.x + o];
        __syncthreads();
    }
    r[threadIdx.x] = e / sm[0];
}

// scores[b,c] = sum_n s[b,n,c]   grid: (8, B)
__global__ void colsum_kernel(const float* __restrict__ s) {
    int b = blockIdx.y;
    const float* base = s + ((size_t)b * NN_ + (size_t)blockIdx.x * 128) * CC;
    float acc = 0.f;
    for (int r = 0; r < 128; r++) acc += base[(size_t)r * CC + threadIdx.x];
    atomicAdd(&g_scores[b * CC + threadIdx.x], acc);
}

__global__ void topk_kernel() {
    int b = blockIdx.x, t = threadIdx.x;
    __shared__ float sm[256];
    sm[t] = g_scores[b * CC + t]; __syncthreads();
    float v = sm[t];
    int cnt = 0;
    for (int j = 0; j < CC; j++) {
        float w = sm[j];
        cnt += (w > v) || (w == v && j < t);
    }
    if (cnt == KTOP - 1) g_thresh[b] = v;
}

// s *= gate; write s fp32 + sN hi/lo planes; entropy   grid: (8, B)
__global__ void gate_split_kernel(float* __restrict__ s) {
    int b = blockIdx.y, t = threadIdx.x;
    float xg = (g_scores[b * CC + t] - g_thresh[b]) / TEMPR;
    float gt;
    if (xg >= 0.f) gt = 1.0f / (1.0f + expf(-xg));
    else { float ex = expf(xg); gt = ex / (1.0f + ex); }
    size_t base = ((size_t)b * NN_ + (size_t)blockIdx.x * 128) * CC;
    double e = 0.0;
    for (int r = 0; r < 128; r++) {
        size_t idx = base + (size_t)r * CC + t;
        float v = s[idx] * gt;
        s[idx] = v;
        float h, l;
        tf32_split(v, h, l);
        g_sN_hi[idx] = h; g_sN_lo[idx] = l;
        e += (double)(-v * logf(v + 1e-15f));
    }
    __shared__ double sm[256];
    double tot = block_red_d(e, sm);
    if (t == 0) atomicAdd(&g_ent, tot);
}

// per-batch traces / frobenius sums over [C,C] mats
__global__ void batchred_kernel(const float* __restrict__ adjp) {
    int b = blockIdx.x, t = threadIdx.x;
    const float* P = adjp  + (size_t)b * CC * CC;
    const float* G = g_sts + (size_t)b * CC * CC;
    const float* U = g_U   + (size_t)b * CC * CC;
    const float* V = g_V   + (size_t)b * CC * CC;
    double trA = 0, ssA = 0, trG = 0, ssG = 0, duv = 0;
    for (int i = t; i < CC * CC; i += 256) {
        float p = P[i]; ssA += (double)p * p;
        float g = G[i]; ssG += (double)g * g;
        duv += (double)U[i] * (double)V[i];
        if (i % (CC + 1) == 0) { trA += p; trG += g; }
    }
    __shared__ double sm[256];
    double r;
    r = block_red_d(trA, sm); if (t == 0) g_trA[b] = r;
    r = block_red_d(ssA, sm); if (t == 0) g_ssA[b] = r;
    r = block_red_d(trG, sm); if (t == 0) g_trG[b] = r;
    r = block_red_d(ssG, sm); if (t == 0) g_ssG[b] = r;
    r = block_red_d(duv, sm); if (t == 0) g_dotUV[b] = r;
}

__global__ void final_kernel(float* __restrict__ o) {
    double linksq = g_sumsq_adj, reconsq = g_sumsq_adj, clusum = 0.0;
    for (int b = 0; b < BB; b++) {
        linksq  += -2.0 * g_trA[b] + g_ssG[b];
        reconsq += -2.0 * g_ssA[b] + g_dotUV[b];
        double nrm = sqrt(g_ssG[b]); if (nrm < 1e-12) nrm = 1e-12;
        double t1 = g_ssG[b] / (nrm * nrm);
        double cb = t1 - 2.0 * g_trG[b] / (nrm * 16.0) + 1.0;   // sqrt(C)=16
        clusum += sqrt(cb > 0.0 ? cb : 0.0);
    }
    double sz = (double)BB * NN_ * NN_;
    o[0] = (float)(sqrt(linksq  > 0.0 ? linksq  : 0.0) / sz);  // link
    o[1] = (float)(g_ent / ((double)BB * NN_));                // ent
    o[2] = (float)(clusum / BB);                               // clu
    o[3] = (float)(sqrt(reconsq > 0.0 ? reconsq : 0.0) / sz);  // recon
}

// ---------------- launch ----------------
#define SYM(p, s) cudaGetSymbolAddress((void**)&p, s)

extern "C" void kernel_launch(void* const* d_in, const int* in_sizes, int n_in,
                              void* d_out, int out_size) {
    const float* x    = (const float*)d_in[0];
    const float* adj  = (const float*)d_in[1];
    const float* Wsrc[6] = { (const float*)d_in[2], (const float*)d_in[4],
                             (const float*)d_in[5], (const float*)d_in[7],
                             (const float*)d_in[9], (const float*)d_in[10] };
    const float* br_p = (const float*)d_in[3];
    const float* bl_p = (const float*)d_in[6];
    const float* br_e = (const float*)d_in[8];
    const float* bl_e = (const float*)d_in[11];

    float* out       = (float*)d_out;
    float* out_xp    = out;                         // [B,C,E]
    float* out_adjp  = out + 2097152;               // [B,C,C]
    float* out_s     = out + 4194304;               // [B,N,C]
    float* out_scal  = out + 12582912;              // link, ent, clu, recon
    float* out_nodex = out + 12582916;              // [B,N,E]

    float *adjNh, *adjNl, *adjTh, *adjTl, *xNh, *xNl, *xTh, *xTl;
    float *aggTh, *aggTl, *hTh, *hTl, *ndxh, *ndxl, *sNh, *sNl;
    float *aTsh, *aTsl, *Wh, *Wl, *apNh, *apNl, *apTh, *apTl;
    float *stsNh, *stsNl, *pre, *sts, *U, *V, *invdeg;
    SYM(adjNh, g_adjN_hi); SYM(adjNl, g_adjN_lo);
    SYM(adjTh, g_adjT_hi); SYM(adjTl, g_adjT_lo);
    SYM(xNh, g_xN_hi); SYM(xNl, g_xN_lo);
    SYM(xTh, g_xT_hi); SYM(xTl, g_xT_lo);
    SYM(aggTh, g_aggT_hi); SYM(aggTl, g_aggT_lo);
    SYM(hTh, g_hT_hi); SYM(hTl, g_hT_lo);
    SYM(ndxh, g_ndx_hi); SYM(ndxl, g_ndx_lo);
    SYM(sNh, g_sN_hi); SYM(sNl, g_sN_lo);
    SYM(aTsh, g_aTs_hi); SYM(aTsl, g_aTs_lo);
    SYM(Wh, g_W_hi); SYM(Wl, g_W_lo);
    SYM(apNh, g_adjpN_hi); SYM(apNl, g_adjpN_lo);
    SYM(apTh, g_adjpT_hi); SYM(apTl, g_adjpT_lo);
    SYM(stsNh, g_stsN_hi); SYM(stsNl, g_stsN_lo);
    SYM(pre, g_pre); SYM(sts, g_sts); SYM(U, g_U); SYM(V, g_V);
    SYM(invdeg, g_invdeg);

    cudaFuncSetAttribute(gemm_tc, cudaFuncAttributeMaxDynamicSharedMemorySize, GSMEM_B);

    init_kernel<<<160, 256>>>();

    // input splits
    nsplit_kernel<<<4096, 256>>>(x, xNh, xNl, 2097152);
    tsplit_kernel<<<dim3(8, 32, 32), 256>>>(x, xTh, xTl, NN_, DD);     // per-batch xT
    for (int w = 0; w < 6; w++)
        nsplit_kernel<<<64, 256>>>(Wsrc[w], Wh + w * 65536, Wl + w * 65536, 16384);
    split_adj_kernel<<<dim3(32, 32, 32), 256>>>(adj);
    invdeg_kernel<<<128, 256>>>();

    // G1': aggT = x^T @ adj^T (/deg per column)   M=256,N=1024,K=1024 per batch
    gemm_tc<<<dim3(8, 2, BB), 256, GSMEM_B>>>(
        xNh, xNl, adjTh, adjTl, nullptr, nullptr, nullptr, nullptr,
        nullptr, aggTh, aggTl, nullptr, invdeg,
        256, 1024, 1024, 1024,
        (size_t)NN_ * DD, (size_t)NN_ * NN_, (size_t)DD * NN_, NN_);

    // ---- embed branch ----
    gemm_tc<<<dim3(2, 8, BB), 256, GSMEM_B>>>(            // pre = agg@Wr_e + x@Wo_e + br_e
        aggTh, aggTl, Wh + 3 * 65536, Wl + 3 * 65536,
        xTh, xTl, Wh + 4 * 65536, Wl + 4 * 65536,
        pre, nullptr, nullptr, br_e, nullptr,
        1024, 256, 256, 256,
        (size_t)DD * NN_, 0, (size_t)NN_ * HH, 0);
    normrelu_t_kernel<<<1024, 256>>>();
    gemm_tc<<<dim3(2, 256, 1), 256, GSMEM_B>>>(           // nodex = h@Wl_e + bl_e
        hTh, hTl, Wh + 5 * 65536, Wl + 5 * 65536,
        nullptr, nullptr, nullptr, nullptr,
        out_nodex, ndxh, ndxl, bl_e, nullptr,
        32768, 256, 256, 256, 0, 0, 0, 0);

    // ---- pool branch ----
    gemm_tc<<<dim3(2, 8, BB), 256, GSMEM_B>>>(            // pre = agg@Wr_p + x@Wo_p + br_p
        aggTh, aggTl, Wh + 0 * 65536, Wl + 0 * 65536,
        xTh, xTl, Wh + 1 * 65536, Wl + 1 * 65536,
        pre, nullptr, nullptr, br_p, nullptr,
        1024, 256, 256, 256,
        (size_t)DD * NN_, 0, (size_t)NN_ * HH, 0);
    normrelu_t_kernel<<<1024, 256>>>();
    gemm_tc<<<dim3(2, 256, 1), 256, GSMEM_B>>>(           // logits = h@Wl_p + bl_p
        hTh, hTl, Wh + 2 * 65536, Wl + 2 * 65536,
        nullptr, nullptr, nullptr, nullptr,
        out_s, nullptr, nullptr, bl_p, nullptr,
        32768, 256, 256, 256, 0, 0, 0, 0);

    // softmax, scores, top-k gate (+entropy, +s planes)
    softmax_kernel<<<BB * NN_, 256>>>(out_s);
    colsum_kernel<<<dim3(8, BB), 256>>>(out_s);
    topk_kernel<<<BB, 256>>>();
    gate_split_kernel<<<dim3(8, BB), 256>>>(out_s);

    // xp = s^T @ nodex    M=C,N=E,K=N
    gemm_tc<<<dim3(2, 2, BB), 256, GSMEM_B>>>(
        sNh, sNl, ndxh, ndxl, nullptr, nullptr, nullptr, nullptr,
        out_xp, nullptr, nullptr, nullptr, nullptr,
        256, 256, 256, 1024,
        (size_t)NN_ * CC, (size_t)NN_ * EE, (size_t)CC * EE, 0);

    // aTs = adj^T @ s     M=N,N=C,K=N  (natural output = sTa^T)
    gemm_tc<<<dim3(2, 8, BB), 256, GSMEM_B>>>(
        adjNh, adjNl, sNh, sNl, nullptr, nullptr, nullptr, nullptr,
        nullptr, aTsh, aTsl, nullptr, nullptr,
        1024, 256, 256, 1024,
        (size_t)NN_ * NN_, (size_t)NN_ * CC, (size_t)NN_ * CC, 0);

    // adj_p = aTs^T @ s   M=C,N=C,K=N
    gemm_tc<<<dim3(2, 2, BB), 256, GSMEM_B>>>(
        aTsh, aTsl, sNh, sNl, nullptr, nullptr, nullptr, nullptr,
        out_adjp, apNh, apNl, nullptr, nullptr,
        256, 256, 256, 1024,
        (size_t)NN_ * CC, (size_t)NN_ * CC, (size_t)CC * CC, 0);

    // sts = s^T @ s       M=C,N=C,K=N
    gemm_tc<<<dim3(2, 2, BB), 256, GSMEM_B>>>(
        sNh, sNl, sNh, sNl, nullptr, nullptr, nullptr, nullptr,
        sts, stsNh, stsNl, nullptr, nullptr,
        256, 256, 256, 1024,
        (size_t)NN_ * CC, (size_t)NN_ * CC, (size_t)CC * CC, 0);

    // adjp^T planes for U
    tsplit_kernel<<<dim3(8, 8, 32), 256>>>(out_adjp, apTh, apTl, CC, CC);

    // U = adjp @ sts ;  V = sts @ adjp   (sts symmetric -> stsN is its own A-plane)
    gemm_tc<<<dim3(2, 2, BB), 256, GSMEM_B>>>(
        apTh, apTl, stsNh, stsNl, nullptr, nullptr, nullptr, nullptr,
        U, nullptr, nullptr, nullptr, nullptr,
        256, 256, 256, 256,
        (size_t)CC * CC, (size_t)CC * CC, (size_t)CC * CC, 0);
    gemm_tc<<<dim3(2, 2, BB), 256, GSMEM_B>>>(
        stsNh, stsNl, apNh, apNl, nullptr, nullptr, nullptr, nullptr,
        V, nullptr, nullptr, nullptr, nullptr,
        256, 256, 256, 256,
        (size_t)CC * CC, (size_t)CC * CC, (size_t)CC * CC, 0);

    // scalar losses
    batchred_kernel<<<BB, 256>>>(out_adjp);
    final_kernel<<<1, 1>>>(out_scal);
}

// round 13
// speedup vs baseline: 1.4945x; 1.0097x over previous
#include <cuda_runtime.h>
#include <math.h>
#include <stdint.h>

// Problem constants
#define BB   32
#define NN_  1024
#define DD   256
#define HH   256
#define EE   256
#define CC   256
#define KTOP 128
#define TEMPR 0.1f

// ---------------- scratch (device globals; no allocation allowed) ----------------
// tf32 hi/lo operand planes, ALL natural orientation
__device__ float g_adjN_hi[33554432], g_adjN_lo[33554432];   // [b][n][m]
__device__ float g_xN_hi[8388608],   g_xN_lo[8388608];       // [b][n][d]
__device__ float g_aggN_hi[8388608], g_aggN_lo[8388608];     // [b][n][d]
__device__ float g_h_hi[8388608],    g_h_lo[8388608];        // [node][h]
__device__ float g_ndx_hi[8388608],  g_ndx_lo[8388608];      // [node][e]
__device__ float g_sN_hi[8388608],   g_sN_lo[8388608];       // [b][n][c]
__device__ float g_aTs_hi[8388608],  g_aTs_lo[8388608];      // [b][m][c]
__device__ float g_W_hi[6 * 65536],  g_W_lo[6 * 65536];      // 0Wr_p 1Wo_p 2Wl_p 3Wr_e 4Wo_e 5Wl_e
__device__ float g_apN_hi[2097152],  g_apN_lo[2097152];      // adj_p planes
__device__ float g_stsN_hi[2097152], g_stsN_lo[2097152];     // sts planes
__device__ float g_pre[8388608];
__device__ float g_sts[2097152], g_U[2097152], g_V[2097152];
__device__ float g_invdeg[BB * NN_];
__device__ float g_scores[BB * CC];
__device__ float g_thresh[BB];
__device__ double g_sumsq_adj;
__device__ double g_ent;
__device__ double g_trA[BB], g_ssA[BB], g_trG[BB], g_ssG[BB], g_dotUV[BB];

// ---------------- helpers ----------------
__device__ __forceinline__ double block_red_d(double v, double* sm) {
    int t = threadIdx.x;
    sm[t] = v; __syncthreads();
    for (int o = 128; o > 0; o >>= 1) {
        if (t < o) sm[t] += sm[t + o];
        __syncthreads();
    }
    double r = sm[0]; __syncthreads();
    return r;
}

__device__ __forceinline__ void cp16(void* s, const void* g) {
    uint32_t si = (uint32_t)__cvta_generic_to_shared(s);
    asm volatile("cp.async.cg.shared.global [%0], [%1], 16;\n" :: "r"(si), "l"(g));
}
__device__ __forceinline__ void cp_commit() {
    asm volatile("cp.async.commit_group;\n" ::);
}

// tf32 hi/lo split: f = hi + lo (+ ~2^-23 f)
__device__ __forceinline__ void tf32_split(float f, float& hi, float& lo) {
    uint32_t h, l;
    asm("cvt.rna.tf32.f32 %0, %1;" : "=r"(h) : "f"(f));
    float r = f - __uint_as_float(h);
    asm("cvt.rna.tf32.f32 %0, %1;" : "=r"(l) : "f"(r));
    hi = __uint_as_float(h);
    lo = __uint_as_float(l);
}

__device__ __forceinline__ void mma8(float* d, const uint32_t* a, const uint32_t* b) {
    asm volatile(
        "mma.sync.aligned.m16n8k8.row.col.f32.tf32.tf32.f32 "
        "{%0,%1,%2,%3},{%4,%5,%6,%7},{%8,%9},{%0,%1,%2,%3};"
        : "+f"(d[0]), "+f"(d[1]), "+f"(d[2]), "+f"(d[3])
        : "r"(a[0]), "r"(a[1]), "r"(a[2]), "r"(a[3]), "r"(b[0]), "r"(b[1]));
}

__global__ void init_kernel() {
    int i = blockIdx.x * blockDim.x + threadIdx.x;
    if (i < BB * CC) g_scores[i] = 0.0f;
    if (i == 0) { g_sumsq_adj = 0.0; g_ent = 0.0; }
}

// natural elementwise split (float4 grid-stride)
__global__ void nsplit_kernel(const float* __restrict__ in,
                              float* __restrict__ hi, float* __restrict__ lo, int n4) {
    for (int i = blockIdx.x * blockDim.x + threadIdx.x; i < n4;
         i += gridDim.x * blockDim.x) {
        float4 v = ((const float4*)in)[i];
        float4 h, l;
        tf32_split(v.x, h.x, l.x); tf32_split(v.y, h.y, l.y);
        tf32_split(v.z, h.z, l.z); tf32_split(v.w, h.w, l.w);
        ((float4*)hi)[i] = h;
        ((float4*)lo)[i] = l;
    }
}

// adj pass: natural split + invdeg + sumsq, one coalesced read, block per row
__global__ void split_adj_kernel(const float* __restrict__ adj) {
    int b = blockIdx.y, n = blockIdx.x, t = threadIdx.x;
    size_t o4 = (((size_t)b * NN_ + n) * NN_) / 4 + t;
    float4 v = ((const float4*)adj)[o4];
    float4 h, l;
    tf32_split(v.x, h.x, l.x); tf32_split(v.y, h.y, l.y);
    tf32_split(v.z, h.z, l.z); tf32_split(v.w, h.w, l.w);
    ((float4*)g_adjN_hi)[o4] = h;
    ((float4*)g_adjN_lo)[o4] = l;
    float rs = v.x + v.y + v.z + v.w;
    float ss = v.x * v.x + v.y * v.y + v.z * v.z + v.w * v.w;
    __shared__ float smf[256];
    __shared__ double smd[256];
    smf[t] = rs; __syncthreads();
    for (int o = 128; o > 0; o >>= 1) {
        if (t < o) smf[t] += smf[t + o];
        __syncthreads();
    }
    if (t == 0) g_invdeg[b * NN_ + n] = 1.0f / fmaxf(smf[0], 1.0f);
    double tot = block_red_d((double)ss, smd);
    if (t == 0) atomicAdd(&g_sumsq_adj, tot);
}

// ---------------- pure-plane tensor-core GEMM (128x128x16, tf32 3x) -------------
// AMAJ=true : A planes natural [row=m][k], ldA = row stride (pad-20 smem tile)
// AMAJ=false: A planes k-major [k][m],    ldA = k-row stride ([16][136] smem tile)
// B planes always k-major [k][n]. 8 warps = 2(m) x 4(n); warp tile 64x32.
#define GSMEM_B (2 * 9472 * 4)

template<bool AMAJ>
__global__ __launch_bounds__(256, 2) void gemm_tc(
    const float* __restrict__ Ahi, const float* __restrict__ Alo,
    const float* __restrict__ Bhi, const float* __restrict__ Blo,
    const float* __restrict__ A2hi, const float* __restrict__ A2lo,
    const float* __restrict__ B2hi, const float* __restrict__ B2lo,
    float* __restrict__ C, float* __restrict__ Chi, float* __restrict__ Clo,
    const float* __restrict__ bias, const float* __restrict__ rowmul,
    int ldA, int ldB, int Nn, int Kd,
    size_t sA, size_t sB, size_t sC, size_t sRm)
{
    constexpr int AP    = AMAJ ? 2560 : 2176;   // one A plane (floats)
    constexpr int STAGE = 2 * AP + 2 * 2176;
    extern __shared__ float smem[];

    int bz = blockIdx.z;
    int bm = blockIdx.y * 128, bn = blockIdx.x * 128;
    int tid = threadIdx.x;
    int lane = tid & 31, wid = tid >> 5;
    int g = lane >> 2, tg = lane & 3;
    int mw = (wid & 1) * 64, nw = (wid >> 1) * 32;

    const float* A1h = Ahi + (size_t)bz * sA;
    const float* A1l = Alo + (size_t)bz * sA;
    const float* B1h = Bhi + (size_t)bz * sB;
    const float* B1l = Blo + (size_t)bz * sB;
    const float* A2h = A2hi ? A2hi + (size_t)bz * sA : nullptr;
    const float* A2l = A2hi ? A2lo + (size_t)bz * sA : nullptr;
    const float* B2h = A2hi ? B2hi + (size_t)bz * sB : nullptr;
    const float* B2l = A2hi ? B2lo + (size_t)bz * sB : nullptr;
    const int T1 = Kd / 16;
    const int T  = A2hi ? 2 * T1 : T1;

    auto issue = [&](int t, int buf) {
        const float *ah, *al, *bh, *bl; int k0;
        if (t < T1) { ah = A1h; al = A1l; bh = B1h; bl = B1l; k0 = t * 16; }
        else        { ah = A2h; al = A2l; bh = B2h; bl = B2l; k0 = (t - T1) * 16; }
        float* S = smem + buf * STAGE;
        if (AMAJ) {
            #pragma unroll
            for (int i = 0; i < 2; i++) {            // A [128][20] m-major
                int id = tid * 2 + i;
                int row = id >> 2, ch = (id & 3) * 4;
                size_t ga = (size_t)(bm + row) * ldA + k0 + ch;
                int so = row * 20 + ch;
                cp16(&S[so],      ah + ga);
                cp16(&S[AP + so], al + ga);
            }
        } else {
            #pragma unroll
            for (int i = 0; i < 2; i++) {            // A [16][136] k-major
                int id = tid * 2 + i;
                int r = id >> 5, c = (id & 31) * 4;
                size_t ga = (size_t)(k0 + r) * ldA + bm + c;
                int so = r * 136 + c;
                cp16(&S[so],      ah + ga);
                cp16(&S[AP + so], al + ga);
            }
        }
        #pragma unroll
        for (int i = 0; i < 2; i++) {                // B [16][136]
            int id = tid * 2 + i;
            int r = id >> 5, c = (id & 31) * 4;
            size_t gb = (size_t)(k0 + r) * ldB + bn + c;
            int so = r * 136 + c;
            cp16(&S[2 * AP + so],        bh + gb);
            cp16(&S[2 * AP + 2176 + so], bl + gb);
        }
        cp_commit();
    };

    float d[4][4][4];
    #pragma unroll
    for (int i = 0; i < 4; i++)
        #pragma unroll
        for (int j = 0; j < 4; j++)
            #pragma unroll
            for (int q = 0; q < 4; q++) d[i][j][q] = 0.0f;

    issue(0, 0);
    issue(1, 1);

    for (int t = 0; t < T; t++) {
        if (t + 1 < T) asm volatile("cp.async.wait_group 1;\n" ::);
        else           asm volatile("cp.async.wait_group 0;\n" ::);
        __syncthreads();

        const float* S  = smem + (t & 1) * STAGE;
        const float* Ah = S;
        const float* Al = S + AP;
        const float* Bh = S + 2 * AP;
        const float* Bl = S + 2 * AP + 2176;

        #pragma unroll
        for (int ks = 0; ks < 16; ks += 8) {
            int kro = (ks + tg) * 136;
            uint32_t bh[4][2], bl4[4][2];
            #pragma unroll
            for (int nt = 0; nt < 4; nt++) {
                int o = kro + nw + nt * 8 + g;
                bh[nt][0]  = __float_as_uint(Bh[o]);
                bh[nt][1]  = __float_as_uint(Bh[o + 544]);
                bl4[nt][0] = __float_as_uint(Bl[o]);
                bl4[nt][1] = __float_as_uint(Bl[o + 544]);
            }
            #pragma unroll
            for (int mt = 0; mt < 4; mt++) {
                uint32_t ah[4], al4[4];
                if (AMAJ) {
                    int mo = (mw + mt * 16 + g) * 20 + ks + tg;
                    ah[0]  = __float_as_uint(Ah[mo]);
                    ah[1]  = __float_as_uint(Ah[mo + 160]);     // m+8
                    ah[2]  = __float_as_uint(Ah[mo + 4]);       // k+4
                    ah[3]  = __float_as_uint(Ah[mo + 164]);
                    al4[0] = __float_as_uint(Al[mo]);
                    al4[1] = __float_as_uint(Al[mo + 160]);
                    al4[2] = __float_as_uint(Al[mo + 4]);
                    al4[3] = __float_as_uint(Al[mo + 164]);
                } else {
                    int o = kro + mw + mt * 16 + g;
                    ah[0]  = __float_as_uint(Ah[o]);
                    ah[1]  = __float_as_uint(Ah[o + 8]);
                    ah[2]  = __float_as_uint(Ah[o + 544]);
                    ah[3]  = __float_as_uint(Ah[o + 552]);
                    al4[0] = __float_as_uint(Al[o]);
                    al4[1] = __float_as_uint(Al[o + 8]);
                    al4[2] = __float_as_uint(Al[o + 544]);
                    al4[3] = __float_as_uint(Al[o + 552]);
                }
                #pragma unroll
                for (int nt = 0; nt < 4; nt++) {
                    mma8(d[mt][nt], ah, bh[nt]);
                    mma8(d[mt][nt], al4, bh[nt]);
                    mma8(d[mt][nt], ah, bl4[nt]);
                }
            }
        }
        __syncthreads();
        if (t + 2 < T) issue(t + 2, t & 1);
    }

    // epilogue: optional rowmul, bias, fp32 C, hi/lo plane outputs
    #pragma unroll
    for (int mt = 0; mt < 4; mt++) {
        int r0 = bm + mw + mt * 16 + g;
        float rm0 = 1.0f, rm8 = 1.0f;
        if (rowmul) {
            rm0 = rowmul[bz * sRm + r0];
            rm8 = rowmul[bz * sRm + r0 + 8];
        }
        #pragma unroll
        for (int nt = 0; nt < 4; nt++) {
            int c = bn + nw + nt * 8 + tg * 2;
            float2 v0, v8;
            v0.x = d[mt][nt][0]; v0.y = d[mt][nt][1];
            v8.x = d[mt][nt][2]; v8.y = d[mt][nt][3];
            if (rowmul) { v0.x *= rm0; v0.y *= rm0; v8.x *= rm8; v8.y *= rm8; }
            if (bias) {
                float2 bb = *(const float2*)&bias[c];
                v0.x += bb.x; v0.y += bb.y; v8.x += bb.x; v8.y += bb.y;
            }
            size_t o0 = (size_t)bz * sC + (size_t)r0 * Nn + c;
            size_t o8 = o0 + (size_t)8 * Nn;
            if (C) {
                *(float2*)&C[o0] = v0;
                *(float2*)&C[o8] = v8;
            }
            if (Chi) {
                float2 h0, l0, h8, l8;
                tf32_split(v0.x, h0.x, l0.x); tf32_split(v0.y, h0.y, l0.y);
                tf32_split(v8.x, h8.x, l8.x); tf32_split(v8.y, h8.y, l8.y);
                *(float2*)&Chi[o0] = h0; *(float2*)&Clo[o0] = l0;
                *(float2*)&Chi[o8] = h8; *(float2*)&Clo[o8] = l8;
            }
        }
    }
}

// normrelu + split, natural: pre[row][256] -> h hi/lo planes natural
__global__ void normrelu_split_kernel() {
    size_t row = blockIdx.x;
    int t = threadIdx.x;
    float v = g_pre[row * HH + t];
    __shared__ float sm[256];
    sm[t] = v * v; __syncthreads();
    for (int o = 128; o > 0; o >>= 1) {
        if (t < o) sm[t] += sm[t + o];
        __syncthreads();
    }
    float rn = 1.0f / fmaxf(sqrtf(sm[0]), 1e-12f);
    float r = fmaxf(v, 0.0f) * rn;
    float h, l;
    tf32_split(r, h, l);
    g_h_hi[row * HH + t] = h;
    g_h_lo[row * HH + t] = l;
}

// softmax over last dim (256), in place
__global__ void softmax_kernel(float* __restrict__ s) {
    size_t row = blockIdx.x;
    float* r = s + row * CC;
    float v = r[threadIdx.x];
    __shared__ float sm[256];
    sm[threadIdx.x] = v; __syncthreads();
    for (int o = 128; o > 0; o >>= 1) {
        if (threadIdx.x < o) sm[threadIdx.x] = fmaxf(sm[threadIdx.x], sm[threadIdx.x + o]);
        __syncthreads();
    }
    float mx = sm[0]; __syncthreads();
    float e = expf(v - mx);
    sm[threadIdx.x] = e; __syncthreads();
    for (int o = 128; o > 0; o >>= 1) {
        if (threadIdx.x < o) sm[threadIdx.x] += sm[threadIdx.x + o];
        __syncthreads();
    }
    r[threadIdx.x] = e / sm[0];
}

// scores[b,c] = sum_n s[b,n,c]   grid: (8, B)
__global__ void colsum_kernel(const float* __restrict__ s) {
    int b = blockIdx.y;
    const float* base = s + ((size_t)b * NN_ + (size_t)blockIdx.x * 128) * CC;
    float acc = 0.f;
    for (int r = 0; r < 128; r++) acc += base[(size_t)r * CC + threadIdx.x];
    atomicAdd(&g_scores[b * CC + threadIdx.x], acc);
}

__global__ void topk_kernel() {
    int b = blockIdx.x, t = threadIdx.x;
    __shared__ float sm[256];
    sm[t] = g_scores[b * CC + t]; __syncthreads();
    float v = sm[t];
    int cnt = 0;
    for (int j = 0; j < CC; j++) {
        float w = sm[j];
        cnt += (w > v) || (w == v && j < t);
    }
    if (cnt == KTOP - 1) g_thresh[b] = v;
}

// s *= gate; write s fp32 + sN hi/lo planes; entropy   grid: (8, B)
__global__ void gate_split_kernel(float* __restrict__ s) {
    int b = blockIdx.y, t = threadIdx.x;
    float xg = (g_scores[b * CC + t] - g_thresh[b]) / TEMPR;
    float gt;
    if (xg >= 0.f) gt = 1.0f / (1.0f + expf(-xg));
    else { float ex = expf(xg); gt = ex / (1.0f + ex); }
    size_t base = ((size_t)b * NN_ + (size_t)blockIdx.x * 128) * CC;
    double e = 0.0;
    for (int r = 0; r < 128; r++) {
        size_t idx = base + (size_t)r * CC + t;
        float v = s[idx] * gt;
        s[idx] = v;
        float h, l;
        tf32_split(v, h, l);
        g_sN_hi[idx] = h; g_sN_lo[idx] = l;
        e += (double)(-v * logf(v + 1e-15f));
    }
    __shared__ double sm[256];
    double tot = block_red_d(e, sm);
    if (t == 0) atomicAdd(&g_ent, tot);
}

// per-batch traces / frobenius sums over [C,C] mats
__global__ void batchred_kernel(const float* __restrict__ adjp) {
    int b = blockIdx.x, t = threadIdx.x;
    const float* P = adjp  + (size_t)b * CC * CC;
    const float* G = g_sts + (size_t)b * CC * CC;
    const float* U = g_U   + (size_t)b * CC * CC;
    const float* V = g_V   + (size_t)b * CC * CC;
    double trA = 0, ssA = 0, trG = 0, ssG = 0, duv = 0;
    for (int i = t; i < CC * CC; i += 256) {
        float p = P[i]; ssA += (double)p * p;
        float g = G[i]; ssG += (double)g * g;
        duv += (double)U[i] * (double)V[i];
        if (i % (CC + 1) == 0) { trA += p; trG += g; }
    }
    __shared__ double sm[256];
    double r;
    r = block_red_d(trA, sm); if (t == 0) g_trA[b] = r;
    r = block_red_d(ssA, sm); if (t == 0) g_ssA[b] = r;
    r = block_red_d(trG, sm); if (t == 0) g_trG[b] = r;
    r = block_red_d(ssG, sm); if (t == 0) g_ssG[b] = r;
    r = block_red_d(duv, sm); if (t == 0) g_dotUV[b] = r;
}

__global__ void final_kernel(float* __restrict__ o) {
    double linksq = g_sumsq_adj, reconsq = g_sumsq_adj, clusum = 0.0;
    for (int b = 0; b < BB; b++) {
        linksq  += -2.0 * g_trA[b] + g_ssG[b];
        reconsq += -2.0 * g_ssA[b] + g_dotUV[b];
        double nrm = sqrt(g_ssG[b]); if (nrm < 1e-12) nrm = 1e-12;
        double t1 = g_ssG[b] / (nrm * nrm);
        double cb = t1 - 2.0 * g_trG[b] / (nrm * 16.0) + 1.0;   // sqrt(C)=16
        clusum += sqrt(cb > 0.0 ? cb : 0.0);
    }
    double sz = (double)BB * NN_ * NN_;
    o[0] = (float)(sqrt(linksq  > 0.0 ? linksq  : 0.0) / sz);  // link
    o[1] = (float)(g_ent / ((double)BB * NN_));                // ent
    o[2] = (float)(clusum / BB);                               // clu
    o[3] = (float)(sqrt(reconsq > 0.0 ? reconsq : 0.0) / sz);  // recon
}

// ---------------- launch ----------------
#define SYM(p, s) cudaGetSymbolAddress((void**)&p, s)

extern "C" void kernel_launch(void* const* d_in, const int* in_sizes, int n_in,
                              void* d_out, int out_size) {
    const float* x    = (const float*)d_in[0];
    const float* adj  = (const float*)d_in[1];
    const float* Wsrc[6] = { (const float*)d_in[2], (const float*)d_in[4],
                             (const float*)d_in[5], (const float*)d_in[7],
                             (const float*)d_in[9], (const float*)d_in[10] };
    const float* br_p = (const float*)d_in[3];
    const float* bl_p = (const float*)d_in[6];
    const float* br_e = (const float*)d_in[8];
    const float* bl_e = (const float*)d_in[11];

    float* out       = (float*)d_out;
    float* out_xp    = out;                         // [B,C,E]
    float* out_adjp  = out + 2097152;               // [B,C,C]
    float* out_s     = out + 4194304;               // [B,N,C]
    float* out_scal  = out + 12582912;              // link, ent, clu, recon
    float* out_nodex = out + 12582916;              // [B,N,E]

    float *adjNh, *adjNl, *xNh, *xNl, *aggNh, *aggNl, *hh, *hl;
    float *ndxh, *ndxl, *sNh, *sNl, *aTsh, *aTsl, *Wh, *Wl;
    float *apNh, *apNl, *stsNh, *stsNl, *pre, *sts, *U, *V, *invdeg;
    SYM(adjNh, g_adjN_hi); SYM(adjNl, g_adjN_lo);
    SYM(xNh, g_xN_hi); SYM(xNl, g_xN_lo);
    SYM(aggNh, g_aggN_hi); SYM(aggNl, g_aggN_lo);
    SYM(hh, g_h_hi); SYM(hl, g_h_lo);
    SYM(ndxh, g_ndx_hi); SYM(ndxl, g_ndx_lo);
    SYM(sNh, g_sN_hi); SYM(sNl, g_sN_lo);
    SYM(aTsh, g_aTs_hi); SYM(aTsl, g_aTs_lo);
    SYM(Wh, g_W_hi); SYM(Wl, g_W_lo);
    SYM(apNh, g_apN_hi); SYM(apNl, g_apN_lo);
    SYM(stsNh, g_stsN_hi); SYM(stsNl, g_stsN_lo);
    SYM(pre, g_pre); SYM(sts, g_sts); SYM(U, g_U); SYM(V, g_V);
    SYM(invdeg, g_invdeg);

    cudaFuncSetAttribute(gemm_tc<true>,  cudaFuncAttributeMaxDynamicSharedMemorySize, GSMEM_B);
    cudaFuncSetAttribute(gemm_tc<false>, cudaFuncAttributeMaxDynamicSharedMemorySize, GSMEM_B);

    init_kernel<<<32, 256>>>();

    // input splits (all natural)
    nsplit_kernel<<<4096, 256>>>(x, xNh, xNl, 2097152);
    for (int w = 0; w < 6; w++)
        nsplit_kernel<<<64, 256>>>(Wsrc[w], Wh + w * 65536, Wl + w * 65536, 16384);
    split_adj_kernel<<<dim3(NN_, BB), 256>>>(adj);

    // agg = (adj @ x) * invdeg(row)    AMAJ: A=adjN [n][m], B=xN [m][d]
    gemm_tc<true><<<dim3(2, 8, BB), 256, GSMEM_B>>>(
        adjNh, adjNl, xNh, xNl, nullptr, nullptr, nullptr, nullptr,
        nullptr, aggNh, aggNl, nullptr, invdeg,
        1024, 256, 256, 1024,
        (size_t)NN_ * NN_, (size_t)NN_ * DD, (size_t)NN_ * DD, NN_);

    // ---- embed branch ----
    gemm_tc<true><<<dim3(2, 256, 1), 256, GSMEM_B>>>(     // pre = agg@Wr_e + x@Wo_e + br_e
        aggNh, aggNl, Wh + 3 * 65536, Wl + 3 * 65536,
        xNh, xNl, Wh + 4 * 65536, Wl + 4 * 65536,
        pre, nullptr, nullptr, br_e, nullptr,
        256, 256, 256, 256, 0, 0, 0, 0);
    normrelu_split_kernel<<<BB * NN_, 256>>>();
    gemm_tc<true><<<dim3(2, 256, 1), 256, GSMEM_B>>>(     // nodex = h@Wl_e + bl_e
        hh, hl, Wh + 5 * 65536, Wl + 5 * 65536,
        nullptr, nullptr, nullptr, nullptr,
        out_nodex, ndxh, ndxl, bl_e, nullptr,
        256, 256, 256, 256, 0, 0, 0, 0);

    // ---- pool branch ----
    gemm_tc<true><<<dim3(2, 256, 1), 256, GSMEM_B>>>(     // pre = agg@Wr_p + x@Wo_p + br_p
        aggNh, aggNl, Wh + 0 * 65536, Wl + 0 * 65536,
        xNh, xNl, Wh + 1 * 65536, Wl + 1 * 65536,
        pre, nullptr, nullptr, br_p, nullptr,
        256, 256, 256, 256, 0, 0, 0, 0);
    normrelu_split_kernel<<<BB * NN_, 256>>>();
    gemm_tc<true><<<dim3(2, 256, 1), 256, GSMEM_B>>>(     // logits = h@Wl_p + bl_p
        hh, hl, Wh + 2 * 65536, Wl + 2 * 65536,
        nullptr, nullptr, nullptr, nullptr,
        out_s, nullptr, nullptr, bl_p, nullptr,
        256, 256, 256, 256, 0, 0, 0, 0);

    // softmax, scores, top-k gate (+entropy, +s planes)
    softmax_kernel<<<BB * NN_, 256>>>(out_s);
    colsum_kernel<<<dim3(8, BB), 256>>>(out_s);
    topk_kernel<<<BB, 256>>>();
    gate_split_kernel<<<dim3(8, BB), 256>>>(out_s);

    // xp = s^T @ nodex    (A k-major view of sN)
    gemm_tc<false><<<dim3(2, 2, BB), 256, GSMEM_B>>>(
        sNh, sNl, ndxh, ndxl, nullptr, nullptr, nullptr, nullptr,
        out_xp, nullptr, nullptr, nullptr, nullptr,
        256, 256, 256, 1024,
        (size_t)NN_ * CC, (size_t)NN_ * EE, (size_t)CC * EE, 0);

    // aTs = adj^T @ s     (A k-major view of adjN)
    gemm_tc<false><<<dim3(2, 8, BB), 256, GSMEM_B>>>(
        adjNh, adjNl, sNh, sNl, nullptr, nullptr, nullptr, nullptr,
        nullptr, aTsh, aTsl, nullptr, nullptr,
        1024, 256, 256, 1024,
        (size_t)NN_ * NN_, (size_t)NN_ * CC, (size_t)NN_ * CC, 0);

    // adj_p = aTs^T @ s
    gemm_tc<false><<<dim3(2, 2, BB), 256, GSMEM_B>>>(
        aTsh, aTsl, sNh, sNl, nullptr, nullptr, nullptr, nullptr,
        out_adjp, apNh, apNl, nullptr, nullptr,
        256, 256, 256, 1024,
        (size_t)NN_ * CC, (size_t)NN_ * CC, (size_t)CC * CC, 0);

    // sts = s^T @ s
    gemm_tc<false><<<dim3(2, 2, BB), 256, GSMEM_B>>>(
        sNh, sNl, sNh, sNl, nullptr, nullptr, nullptr, nullptr,
        sts, stsNh, stsNl, nullptr, nullptr,
        256, 256, 256, 1024,
        (size_t)NN_ * CC, (size_t)NN_ * CC, (size_t)CC * CC, 0);

    // U = adjp @ sts ; V = sts @ adjp   (AMAJ natural planes; no transposes needed)
    gemm_tc<true><<<dim3(2, 2, BB), 256, GSMEM_B>>>(
        apNh, apNl, stsNh, stsNl, nullptr, nullptr, nullptr, nullptr,
        U, nullptr, nullptr, nullptr, nullptr,
        256, 256, 256, 256,
        (size_t)CC * CC, (size_t)CC * CC, (size_t)CC * CC, 0);
    gemm_tc<true><<<dim3(2, 2, BB), 256, GSMEM_B>>>(
        stsNh, stsNl, apNh, apNl, nullptr, nullptr, nullptr, nullptr,
        V, nullptr, nullptr, nullptr, nullptr,
        256, 256, 256, 256,
        (size_t)CC * CC, (size_t)CC * CC, (size_t)CC * CC, 0);

    // scalar losses
    batchred_kernel<<<BB, 256>>>(out_adjp);
    final_kernel<<<1, 1>>>(out_scal);
}

// round 15
// speedup vs baseline: 1.8008x; 1.2050x over previous
#include <cuda_runtime.h>
#include <math.h>
#include <stdint.h>

// Problem constants
#define BB   32
#define NN_  1024
#define DD   256
#define HH   256
#define EE   256
#define CC   256
#define KTOP 128
#define TEMPR 0.1f

// ---------------- scratch (device globals; no allocation allowed) ----------------
// tf32 hi/lo operand planes, ALL natural orientation
__device__ float g_adjN_hi[33554432], g_adjN_lo[33554432];   // [b][n][m]
__device__ float g_xN_hi[8388608],   g_xN_lo[8388608];       // [b][n][d]
__device__ float g_aggN_hi[8388608], g_aggN_lo[8388608];     // [b][n][d]
__device__ float g_h_hi[8388608],    g_h_lo[8388608];        // [node][h]
__device__ float g_ndx_hi[8388608],  g_ndx_lo[8388608];      // [node][e]
__device__ float g_sN_hi[8388608],   g_sN_lo[8388608];       // [b][n][c]
__device__ float g_aTs_hi[8388608],  g_aTs_lo[8388608];      // [b][m][c]
__device__ float g_W_hi[6 * 65536],  g_W_lo[6 * 65536];      // 0Wr_p 1Wo_p 2Wl_p 3Wr_e 4Wo_e 5Wl_e
__device__ float g_apN_hi[2097152],  g_apN_lo[2097152];      // adj_p planes
__device__ float g_stsN_hi[2097152], g_stsN_lo[2097152];     // sts planes
__device__ float g_pre[8388608];
__device__ float g_sts[2097152], g_U[2097152], g_V[2097152];
__device__ float g_invdeg[BB * NN_];
__device__ float g_scores[BB * CC];
__device__ float g_thresh[BB];
__device__ double g_sumsq_adj;
__device__ double g_ent;
__device__ double g_trA[BB], g_ssA[BB], g_trG[BB], g_ssG[BB], g_dotUV[BB];

// ---------------- helpers ----------------
__device__ __forceinline__ double block_red_d(double v, double* sm) {
    int t = threadIdx.x;
    sm[t] = v; __syncthreads();
    for (int o = 128; o > 0; o >>= 1) {
        if (t < o) sm[t] += sm[t + o];
        __syncthreads();
    }
    double r = sm[0]; __syncthreads();
    return r;
}

__device__ __forceinline__ void cp16(void* s, const void* g) {
    uint32_t si = (uint32_t)__cvta_generic_to_shared(s);
    asm volatile("cp.async.cg.shared.global [%0], [%1], 16;\n" :: "r"(si), "l"(g));
}
__device__ __forceinline__ void cp_commit() {
    asm volatile("cp.async.commit_group;\n" ::);
}

// tf32 hi/lo split: f = hi + lo (+ ~2^-23 f)
__device__ __forceinline__ void tf32_split(float f, float& hi, float& lo) {
    uint32_t h, l;
    asm("cvt.rna.tf32.f32 %0, %1;" : "=r"(h) : "f"(f));
    float r = f - __uint_as_float(h);
    asm("cvt.rna.tf32.f32 %0, %1;" : "=r"(l) : "f"(r));
    hi = __uint_as_float(h);
    lo = __uint_as_float(l);
}

__device__ __forceinline__ void mma8(float* d, const uint32_t* a, const uint32_t* b) {
    asm volatile(
        "mma.sync.aligned.m16n8k8.row.col.f32.tf32.tf32.f32 "
        "{%0,%1,%2,%3},{%4,%5,%6,%7},{%8,%9},{%0,%1,%2,%3};"
        : "+f"(d[0]), "+f"(d[1]), "+f"(d[2]), "+f"(d[3])
        : "r"(a[0]), "r"(a[1]), "r"(a[2]), "r"(a[3]), "r"(b[0]), "r"(b[1]));
}

__global__ void init_kernel() {
    int i = blockIdx.x * blockDim.x + threadIdx.x;
    if (i < BB * CC) g_scores[i] = 0.0f;
    if (i == 0) { g_sumsq_adj = 0.0; g_ent = 0.0; }
}

// natural elementwise split (float4 grid-stride)
__global__ void nsplit_kernel(const float* __restrict__ in,
                              float* __restrict__ hi, float* __restrict__ lo, int n4) {
    for (int i = blockIdx.x * blockDim.x + threadIdx.x; i < n4;
         i += gridDim.x * blockDim.x) {
        float4 v = ((const float4*)in)[i];
        float4 h, l;
        tf32_split(v.x, h.x, l.x); tf32_split(v.y, h.y, l.y);
        tf32_split(v.z, h.z, l.z); tf32_split(v.w, h.w, l.w);
        ((float4*)hi)[i] = h;
        ((float4*)lo)[i] = l;
    }
}

// all six weight matrices in one launch; blockIdx.y selects matrix
// grid must be (64, 6): 64*256 threads = 16384 float4 = 65536 floats per matrix
__global__ void wsplit_kernel(const float* w0, const float* w1, const float* w2,
                              const float* w3, const float* w4, const float* w5) {
    const float* src[6] = {w0, w1, w2, w3, w4, w5};
    int w = blockIdx.y;
    int i = blockIdx.x * blockDim.x + threadIdx.x;        // 0..16383 (float4)
    float4 v = ((const float4*)src[w])[i];
    float4 h, l;
    tf32_split(v.x, h.x, l.x); tf32_split(v.y, h.y, l.y);
    tf32_split(v.z, h.z, l.z); tf32_split(v.w, h.w, l.w);
    ((float4*)(g_W_hi + w * 65536))[i] = h;
    ((float4*)(g_W_lo + w * 65536))[i] = l;
}

// adj pass: natural split + invdeg + sumsq, one coalesced read, block per row
__global__ void split_adj_kernel(const float* __restrict__ adj) {
    int b = blockIdx.y, n = blockIdx.x, t = threadIdx.x;
    size_t o4 = (((size_t)b * NN_ + n) * NN_) / 4 + t;
    float4 v = ((const float4*)adj)[o4];
    float4 h, l;
    tf32_split(v.x, h.x, l.x); tf32_split(v.y, h.y, l.y);
    tf32_split(v.z, h.z, l.z); tf32_split(v.w, h.w, l.w);
    ((float4*)g_adjN_hi)[o4] = h;
    ((float4*)g_adjN_lo)[o4] = l;
    float rs = v.x + v.y + v.z + v.w;
    float ss = v.x * v.x + v.y * v.y + v.z * v.z + v.w * v.w;
    __shared__ float smf[256];
    __shared__ double smd[256];
    smf[t] = rs; __syncthreads();
    for (int o = 128; o > 0; o >>= 1) {
        if (t < o) smf[t] += smf[t + o];
        __syncthreads();
    }
    if (t == 0) g_invdeg[b * NN_ + n] = 1.0f / fmaxf(smf[0], 1.0f);
    double tot = block_red_d((double)ss, smd);
    if (t == 0) atomicAdd(&g_sumsq_adj, tot);
}

// ---------------- pure-plane tensor-core GEMM (128x128x16, tf32 2x) -------------
// 2-product scheme: a*b ~= a_hi*b_hi + a_lo*b_hi  (B lo planes never loaded)
// AMAJ=true : A planes natural [row=m][k], ldA = row stride (pad-20 smem tile)
// AMAJ=false: A planes k-major [k][m],    ldA = k-row stride ([16][136] smem tile)
// B planes always k-major [k][n]. 8 warps = 2(m) x 4(n); warp tile 64x32.
#define GSMEM_B (2 * 7296 * 4)

template<bool AMAJ>
__global__ __launch_bounds__(256, 2) void gemm_tc(
    const float* __restrict__ Ahi, const float* __restrict__ Alo,
    const float* __restrict__ Bhi,
    const float* __restrict__ A2hi, const float* __restrict__ A2lo,
    const float* __restrict__ B2hi,
    float* __restrict__ C, float* __restrict__ Chi, float* __restrict__ Clo,
    const float* __restrict__ bias, const float* __restrict__ rowmul,
    int ldA, int ldB, int Nn, int Kd,
    size_t sA, size_t sB, size_t sC, size_t sRm)
{
    constexpr int AP    = AMAJ ? 2560 : 2176;   // one A plane (floats)
    constexpr int STAGE = 2 * AP + 2176;        // Ahi, Alo, Bhi
    extern __shared__ float smem[];

    int bz = blockIdx.z;
    int bm = blockIdx.y * 128, bn = blockIdx.x * 128;
    int tid = threadIdx.x;
    int lane = tid & 31, wid = tid >> 5;
    int g = lane >> 2, tg = lane & 3;
    int mw = (wid & 1) * 64, nw = (wid >> 1) * 32;

    const float* A1h = Ahi + (size_t)bz * sA;
    const float* A1l = Alo + (size_t)bz * sA;
    const float* B1h = Bhi + (size_t)bz * sB;
    const float* A2h = A2hi ? A2hi + (size_t)bz * sA : nullptr;
    const float* A2l = A2hi ? A2lo + (size_t)bz * sA : nullptr;
    const float* B2h = A2hi ? B2hi + (size_t)bz * sB : nullptr;
    const int T1 = Kd / 16;
    const int T  = A2hi ? 2 * T1 : T1;

    auto issue = [&](int t, int buf) {
        const float *ah, *al, *bh; int k0;
        if (t < T1) { ah = A1h; al = A1l; bh = B1h; k0 = t * 16; }
        else        { ah = A2h; al = A2l; bh = B2h; k0 = (t - T1) * 16; }
        float* S = smem + buf * STAGE;
        if (AMAJ) {
            #pragma unroll
            for (int i = 0; i < 2; i++) {            // A [128][20] m-major
                int id = tid * 2 + i;
                int row = id >> 2, ch = (id & 3) * 4;
                size_t ga = (size_t)(bm + row) * ldA + k0 + ch;
                int so = row * 20 + ch;
                cp16(&S[so],      ah + ga);
                cp16(&S[AP + so], al + ga);
            }
        } else {
            #pragma unroll
            for (int i = 0; i < 2; i++) {            // A [16][136] k-major
                int id = tid * 2 + i;
                int r = id >> 5, c = (id & 31) * 4;
                size_t ga = (size_t)(k0 + r) * ldA + bm + c;
                int so = r * 136 + c;
                cp16(&S[so],      ah + ga);
                cp16(&S[AP + so], al + ga);
            }
        }
        #pragma unroll
        for (int i = 0; i < 2; i++) {                // B hi [16][136]
            int id = tid * 2 + i;
            int r = id >> 5, c = (id & 31) * 4;
            size_t gb = (size_t)(k0 + r) * ldB + bn + c;
            cp16(&S[2 * AP + r * 136 + c], bh + gb);
        }
        cp_commit();
    };

    float d[4][4][4];
    #pragma unroll
    for (int i = 0; i < 4; i++)
        #pragma unroll
        for (int j = 0; j < 4; j++)
            #pragma unroll
            for (int q = 0; q < 4; q++) d[i][j][q] = 0.0f;

    issue(0, 0);
    issue(1, 1);

    for (int t = 0; t < T; t++) {
        if (t + 1 < T) asm volatile("cp.async.wait_group 1;\n" ::);
        else           asm volatile("cp.async.wait_group 0;\n" ::);
        __syncthreads();

        const float* S  = smem + (t & 1) * STAGE;
        const float* Ah = S;
        const float* Al = S + AP;
        const float* Bh = S + 2 * AP;

        #pragma unroll
        for (int ks = 0; ks < 16; ks += 8) {
            int kro = (ks + tg) * 136;
            uint32_t bh[4][2];
            #pragma unroll
            for (int nt = 0; nt < 4; nt++) {
                int o = kro + nw + nt * 8 + g;
                bh[nt][0] = __float_as_uint(Bh[o]);
                bh[nt][1] = __float_as_uint(Bh[o + 544]);
            }
            #pragma unroll
            for (int mt = 0; mt < 4; mt++) {
                uint32_t ah[4], al4[4];
                if (AMAJ) {
                    int mo = (mw + mt * 16 + g) * 20 + ks + tg;
                    ah[0]  = __float_as_uint(Ah[mo]);
                    ah[1]  = __float_as_uint(Ah[mo + 160]);     // m+8
                    ah[2]  = __float_as_uint(Ah[mo + 4]);       // k+4
                    ah[3]  = __float_as_uint(Ah[mo + 164]);
                    al4[0] = __float_as_uint(Al[mo]);
                    al4[1] = __float_as_uint(Al[mo + 160]);
                    al4[2] = __float_as_uint(Al[mo + 4]);
                    al4[3] = __float_as_uint(Al[mo + 164]);
                } else {
                    int o = kro + mw + mt * 16 + g;
                    ah[0]  = __float_as_uint(Ah[o]);
                    ah[1]  = __float_as_uint(Ah[o + 8]);
                    ah[2]  = __float_as_uint(Ah[o + 544]);
                    ah[3]  = __float_as_uint(Ah[o + 552]);
                    al4[0] = __float_as_uint(Al[o]);
                    al4[1] = __float_as_uint(Al[o + 8]);
                    al4[2] = __float_as_uint(Al[o + 544]);
                    al4[3] = __float_as_uint(Al[o + 552]);
                }
                #pragma unroll
                for (int nt = 0; nt < 4; nt++) {
                    mma8(d[mt][nt], ah, bh[nt]);
                    mma8(d[mt][nt], al4, bh[nt]);
                }
            }
        }
        __syncthreads();
        if (t + 2 < T) issue(t + 2, t & 1);
    }

    // epilogue: optional rowmul, bias, fp32 C, hi/lo plane outputs
    #pragma unroll
    for (int mt = 0; mt < 4; mt++) {
        int r0 = bm + mw + mt * 16 + g;
        float rm0 = 1.0f, rm8 = 1.0f;
        if (rowmul) {
            rm0 = rowmul[bz * sRm + r0];
            rm8 = rowmul[bz * sRm + r0 + 8];
        }
        #pragma unroll
        for (int nt = 0; nt < 4; nt++) {
            int c = bn + nw + nt * 8 + tg * 2;
            float2 v0, v8;
            v0.x = d[mt][nt][0]; v0.y = d[mt][nt][1];
            v8.x = d[mt][nt][2]; v8.y = d[mt][nt][3];
            if (rowmul) { v0.x *= rm0; v0.y *= rm0; v8.x *= rm8; v8.y *= rm8; }
            if (bias) {
                float2 bb = *(const float2*)&bias[c];
                v0.x += bb.x; v0.y += bb.y; v8.x += bb.x; v8.y += bb.y;
            }
            size_t o0 = (size_t)bz * sC + (size_t)r0 * Nn + c;
            size_t o8 = o0 + (size_t)8 * Nn;
            if (C) {
                *(float2*)&C[o0] = v0;
                *(float2*)&C[o8] = v8;
            }
            if (Chi) {
                float2 h0, l0, h8, l8;
                tf32_split(v0.x, h0.x, l0.x); tf32_split(v0.y, h0.y, l0.y);
                tf32_split(v8.x, h8.x, l8.x); tf32_split(v8.y, h8.y, l8.y);
                *(float2*)&Chi[o0] = h0; *(float2*)&Clo[o0] = l0;
                *(float2*)&Chi[o8] = h8; *(float2*)&Clo[o8] = l8;
            }
        }
    }
}

// normrelu + split, natural: pre[row][256] -> h hi/lo planes natural
__global__ void normrelu_split_kernel() {
    size_t row = blockIdx.x;
    int t = threadIdx.x;
    float v = g_pre[row * HH + t];
    __shared__ float sm[256];
    sm[t] = v * v; __syncthreads();
    for (int o = 128; o > 0; o >>= 1) {
        if (t < o) sm[t] += sm[t + o];
        __syncthreads();
    }
    float rn = 1.0f / fmaxf(sqrtf(sm[0]), 1e-12f);
    float r = fmaxf(v, 0.0f) * rn;
    float h, l;
    tf32_split(r, h, l);
    g_h_hi[row * HH + t] = h;
    g_h_lo[row * HH + t] = l;
}

// softmax over last dim (256), in place
__global__ void softmax_kernel(float* __restrict__ s) {
    size_t row = blockIdx.x;
    float* r = s + row * CC;
    float v = r[threadIdx.x];
    __shared__ float sm[256];
    sm[threadIdx.x] = v; __syncthreads();
    for (int o = 128; o > 0; o >>= 1) {
        if (threadIdx.x < o) sm[threadIdx.x] = fmaxf(sm[threadIdx.x], sm[threadIdx.x + o]);
        __syncthreads();
    }
    float mx = sm[0]; __syncthreads();
    float e = expf(v - mx);
    sm[threadIdx.x] = e; __syncthreads();
    for (int o = 128; o > 0; o >>= 1) {
        if (threadIdx.x < o) sm[threadIdx.x] += sm[threadIdx.x + o];
        __syncthreads();
    }
    r[threadIdx.x] = e / sm[0];
}

// scores[b,c] = sum_n s[b,n,c]   grid: (8, B)
__global__ void colsum_kernel(const float* __restrict__ s) {
    int b = blockIdx.y;
    const float* base = s + ((size_t)b * NN_ + (size_t)blockIdx.x * 128) * CC;
    float acc = 0.f;
    for (int r = 0; r < 128; r++) acc += base[(size_t)r * CC + threadIdx.x];
    atomicAdd(&g_scores[b * CC + threadIdx.x], acc);
}

__global__ void topk_kernel() {
    int b = blockIdx.x, t = threadIdx.x;
    __shared__ float sm[256];
    sm[t] = g_scores[b * CC + t]; __syncthreads();
    float v = sm[t];
    int cnt = 0;
    for (int j = 0; j < CC; j++) {
        float w = sm[j];
        cnt += (w > v) || (w == v && j < t);
    }
    if (cnt == KTOP - 1) g_thresh[b] = v;
}

// s *= gate; write s fp32 + sN hi/lo planes; entropy   grid: (8, B)
__global__ void gate_split_kernel(float* __restrict__ s) {
    int b = blockIdx.y, t = threadIdx.x;
    float xg = (g_scores[b * CC + t] - g_thresh[b]) / TEMPR;
    float gt;
    if (xg >= 0.f) gt = 1.0f / (1.0f + expf(-xg));
    else { float ex = expf(xg); gt = ex / (1.0f + ex); }
    size_t base = ((size_t)b * NN_ + (size_t)blockIdx.x * 128) * CC;
    double e = 0.0;
    for (int r = 0; r < 128; r++) {
        size_t idx = base + (size_t)r * CC + t;
        float v = s[idx] * gt;
        s[idx] = v;
        float h, l;
        tf32_split(v, h, l);
        g_sN_hi[idx] = h; g_sN_lo[idx] = l;
        e += (double)(-v * logf(v + 1e-15f));
    }
    __shared__ double sm[256];
    double tot = block_red_d(e, sm);
    if (t == 0) atomicAdd(&g_ent, tot);
}

// per-batch traces / frobenius sums over [C,C] mats
__global__ void batchred_kernel(const float* __restrict__ adjp) {
    int b = blockIdx.x, t = threadIdx.x;
    const float* P = adjp  + (size_t)b * CC * CC;
    const float* G = g_sts + (size_t)b * CC * CC;
    const float* U = g_U   + (size_t)b * CC * CC;
    const float* V = g_V   + (size_t)b * CC * CC;
    double trA = 0, ssA = 0, trG = 0, ssG = 0, duv = 0;
    for (int i = t; i < CC * CC; i += 256) {
        float p = P[i]; ssA += (double)p * p;
        float g = G[i]; ssG += (double)g * g;
        duv += (double)U[i] * (double)V[i];
        if (i % (CC + 1) == 0) { trA += p; trG += g; }
    }
    __shared__ double sm[256];
    double r;
    r = block_red_d(trA, sm); if (t == 0) g_trA[b] = r;
    r = block_red_d(ssA, sm); if (t == 0) g_ssA[b] = r;
    r = block_red_d(trG, sm); if (t == 0) g_trG[b] = r;
    r = block_red_d(ssG, sm); if (t == 0) g_ssG[b] = r;
    r = block_red_d(duv, sm); if (t == 0) g_dotUV[b] = r;
}

__global__ void final_kernel(float* __restrict__ o) {
    double linksq = g_sumsq_adj, reconsq = g_sumsq_adj, clusum = 0.0;
    for (int b = 0; b < BB; b++) {
        linksq  += -2.0 * g_trA[b] + g_ssG[b];
        reconsq += -2.0 * g_ssA[b] + g_dotUV[b];
        double nrm = sqrt(g_ssG[b]); if (nrm < 1e-12) nrm = 1e-12;
        double t1 = g_ssG[b] / (nrm * nrm);
        double cb = t1 - 2.0 * g_trG[b] / (nrm * 16.0) + 1.0;   // sqrt(C)=16
        clusum += sqrt(cb > 0.0 ? cb : 0.0);
    }
    double sz = (double)BB * NN_ * NN_;
    o[0] = (float)(sqrt(linksq  > 0.0 ? linksq  : 0.0) / sz);  // link
    o[1] = (float)(g_ent / ((double)BB * NN_));                // ent
    o[2] = (float)(clusum / BB);                               // clu
    o[3] = (float)(sqrt(reconsq > 0.0 ? reconsq : 0.0) / sz);  // recon
}

// ---------------- launch ----------------
#define SYM(p, s) cudaGetSymbolAddress((void**)&p, s)

extern "C" void kernel_launch(void* const* d_in, const int* in_sizes, int n_in,
                              void* d_out, int out_size) {
    const float* x    = (const float*)d_in[0];
    const float* adj  = (const float*)d_in[1];
    const float* br_p = (const float*)d_in[3];
    const float* bl_p = (const float*)d_in[6];
    const float* br_e = (const float*)d_in[8];
    const float* bl_e = (const float*)d_in[11];

    float* out       = (float*)d_out;
    float* out_xp    = out;                         // [B,C,E]
    float* out_adjp  = out + 2097152;               // [B,C,C]
    float* out_s     = out + 4194304;               // [B,N,C]
    float* out_scal  = out + 12582912;              // link, ent, clu, recon
    float* out_nodex = out + 12582916;              // [B,N,E]

    float *adjNh, *adjNl, *xNh, *xNl, *aggNh, *aggNl, *hh, *hl;
    float *ndxh, *ndxl, *sNh, *sNl, *aTsh, *aTsl, *Wh, *Wl;
    float *apNh, *apNl, *stsNh, *stsNl, *pre, *sts, *U, *V, *invdeg;
    SYM(adjNh, g_adjN_hi); SYM(adjNl, g_adjN_lo);
    SYM(xNh, g_xN_hi); SYM(xNl, g_xN_lo);
    SYM(aggNh, g_aggN_hi); SYM(aggNl, g_aggN_lo);
    SYM(hh, g_h_hi); SYM(hl, g_h_lo);
    SYM(ndxh, g_ndx_hi); SYM(ndxl, g_ndx_lo);
    SYM(sNh, g_sN_hi); SYM(sNl, g_sN_lo);
    SYM(aTsh, g_aTs_hi); SYM(aTsl, g_aTs_lo);
    SYM(Wh, g_W_hi); SYM(Wl, g_W_lo);
    SYM(apNh, g_apN_hi); SYM(apNl, g_apN_lo);
    SYM(stsNh, g_stsN_hi); SYM(stsNl, g_stsN_lo);
    SYM(pre, g_pre); SYM(sts, g_sts); SYM(U, g_U); SYM(V, g_V);
    SYM(invdeg, g_invdeg);

    cudaFuncSetAttribute(gemm_tc<true>,  cudaFuncAttributeMaxDynamicSharedMemorySize, GSMEM_B);
    cudaFuncSetAttribute(gemm_tc<false>, cudaFuncAttributeMaxDynamicSharedMemorySize, GSMEM_B);

    init_kernel<<<32, 256>>>();

    // input splits (all natural)
    nsplit_kernel<<<4096, 256>>>(x, xNh, xNl, 2097152);
    wsplit_kernel<<<dim3(64, 6), 256>>>(                   // FIXED: 64 blocks (full coverage)
        (const float*)d_in[2], (const float*)d_in[4], (const float*)d_in[5],
        (const float*)d_in[7], (const float*)d_in[9], (const float*)d_in[10]);
    split_adj_kernel<<<dim3(NN_, BB), 256>>>(adj);

    // agg = (adj @ x) * invdeg(row)    AMAJ: A=adjN [n][m], B=xN [m][d]
    gemm_tc<true><<<dim3(2, 8, BB), 256, GSMEM_B>>>(
        adjNh, adjNl, xNh, nullptr, nullptr, nullptr,
        nullptr, aggNh, aggNl, nullptr, invdeg,
        1024, 256, 256, 1024,
        (size_t)NN_ * NN_, (size_t)NN_ * DD, (size_t)NN_ * DD, NN_);

    // ---- embed branch ----
    gemm_tc<true><<<dim3(2, 256, 1), 256, GSMEM_B>>>(     // pre = agg@Wr_e + x@Wo_e + br_e
        aggNh, aggNl, Wh + 3 * 65536,
        xNh, xNl, Wh + 4 * 65536,
        pre, nullptr, nullptr, br_e, nullptr,
        256, 256, 256, 256, 0, 0, 0, 0);
    normrelu_split_kernel<<<BB * NN_, 256>>>();
    gemm_tc<true><<<dim3(2, 256, 1), 256, GSMEM_B>>>(     // nodex = h@Wl_e + bl_e
        hh, hl, Wh + 5 * 65536,
        nullptr, nullptr, nullptr,
        out_nodex, ndxh, ndxl, bl_e, nullptr,
        256, 256, 256, 256, 0, 0, 0, 0);

    // ---- pool branch ----
    gemm_tc<true><<<dim3(2, 256, 1), 256, GSMEM_B>>>(     // pre = agg@Wr_p + x@Wo_p + br_p
        aggNh, aggNl, Wh + 0 * 65536,
        xNh, xNl, Wh + 1 * 65536,
        pre, nullptr, nullptr, br_p, nullptr,
        256, 256, 256, 256, 0, 0, 0, 0);
    normrelu_split_kernel<<<BB * NN_, 256>>>();
    gemm_tc<true><<<dim3(2, 256, 1), 256, GSMEM_B>>>(     // logits = h@Wl_p + bl_p
        hh, hl, Wh + 2 * 65536,
        nullptr, nullptr, nullptr,
        out_s, nullptr, nullptr, bl_p, nullptr,
        256, 256, 256, 256, 0, 0, 0, 0);

    // softmax, scores, top-k gate (+entropy, +s planes)
    softmax_kernel<<<BB * NN_, 256>>>(out_s);
    colsum_kernel<<<dim3(8, BB), 256>>>(out_s);
    topk_kernel<<<BB, 256>>>();
    gate_split_kernel<<<dim3(8, BB), 256>>>(out_s);

    // xp = s^T @ nodex    (A k-major view of sN)
    gemm_tc<false><<<dim3(2, 2, BB), 256, GSMEM_B>>>(
        sNh, sNl, ndxh, nullptr, nullptr, nullptr,
        out_xp, nullptr, nullptr, nullptr, nullptr,
        256, 256, 256, 1024,
        (size_t)NN_ * CC, (size_t)NN_ * EE, (size_t)CC * EE, 0);

    // aTs = adj^T @ s     (A k-major view of adjN)
    gemm_tc<false><<<dim3(2, 8, BB), 256, GSMEM_B>>>(
        adjNh, adjNl, sNh, nullptr, nullptr, nullptr,
        nullptr, aTsh, aTsl, nullptr, nullptr,
        1024, 256, 256, 1024,
        (size_t)NN_ * NN_, (size_t)NN_ * CC, (size_t)NN_ * CC, 0);

    // adj_p = aTs^T @ s
    gemm_tc<false><<<dim3(2, 2, BB), 256, GSMEM_B>>>(
        aTsh, aTsl, sNh, nullptr, nullptr, nullptr,
        out_adjp, apNh, apNl, nullptr, nullptr,
        256, 256, 256, 1024,
        (size_t)NN_ * CC, (size_t)NN_ * CC, (size_t)CC * CC, 0);

    // sts = s^T @ s
    gemm_tc<false><<<dim3(2, 2, BB), 256, GSMEM_B>>>(
        sNh, sNl, sNh, nullptr, nullptr, nullptr,
        sts, stsNh, stsNl, nullptr, nullptr,
        256, 256, 256, 1024,
        (size_t)NN_ * CC, (size_t)NN_ * CC, (size_t)CC * CC, 0);

    // U = adjp @ sts ; V = sts @ adjp   (AMAJ natural planes)
    gemm_tc<true><<<dim3(2, 2, BB), 256, GSMEM_B>>>(
        apNh, apNl, stsNh, nullptr, nullptr, nullptr,
        U, nullptr, nullptr, nullptr, nullptr,
        256, 256, 256, 256,
        (size_t)CC * CC, (size_t)CC * CC, (size_t)CC * CC, 0);
    gemm_tc<true><<<dim3(2, 2, BB), 256, GSMEM_B>>>(
        stsNh, stsNl, apNh, nullptr, nullptr, nullptr,
        V, nullptr, nullptr, nullptr, nullptr,
        256, 256, 256, 256,
        (size_t)CC * CC, (size_t)CC * CC, (size_t)CC * CC, 0);

    // scalar losses
    batchred_kernel<<<BB, 256>>>(out_adjp);
    final_kernel<<<1, 1>>>(out_scal);
}

// round 16
// speedup vs baseline: 1.8237x; 1.0127x over previous
#include <cuda_runtime.h>
#include <math.h>
#include <stdint.h>

// Problem constants
#define BB   32
#define NN_  1024
#define DD   256
#define HH   256
#define EE   256
#define CC   256
#define KTOP 128
#define TEMPR 0.1f

// ---------------- scratch (device globals; no allocation allowed) ----------------
// tf32 planes, natural orientation. lo planes only where consumed.
__device__ float g_adjN_hi[33554432];                        // [b][n][m]
__device__ float g_xN_hi[8388608],   g_xN_lo[8388608];       // [b][n][d]
__device__ float g_aggN_hi[8388608], g_aggN_lo[8388608];     // [b][n][d]
__device__ float g_h_hi[8388608],    g_h_lo[8388608];        // [node][h]
__device__ float g_ndx_hi[8388608];                          // [node][e]
__device__ float g_sN_hi[8388608],   g_sN_lo[8388608];       // [b][n][c]
__device__ float g_aTs_hi[8388608];                          // [b][m][c]
__device__ float g_W_hi[6 * 65536];                          // 0Wr_p 1Wo_p 2Wl_p 3Wr_e 4Wo_e 5Wl_e
__device__ float g_apN_hi[2097152],  g_apN_lo[2097152];      // adj_p planes
__device__ float g_stsN_hi[2097152];                         // sts plane
__device__ float g_pre[8388608];
__device__ float g_sts[2097152], g_U[2097152], g_V[2097152];
__device__ float g_invdeg[BB * NN_];
__device__ float g_scores[BB * CC];
__device__ float g_thresh[BB];
__device__ double g_sumsq_adj;
__device__ double g_ent;
__device__ double g_trA[BB], g_ssA[BB], g_trG[BB], g_ssG[BB], g_dotUV[BB];

// ---------------- helpers ----------------
__device__ __forceinline__ double block_red_d(double v, double* sm) {
    int t = threadIdx.x;
    sm[t] = v; __syncthreads();
    for (int o = 128; o > 0; o >>= 1) {
        if (t < o) sm[t] += sm[t + o];
        __syncthreads();
    }
    double r = sm[0]; __syncthreads();
    return r;
}

__device__ __forceinline__ void cp16(void* s, const void* g) {
    uint32_t si = (uint32_t)__cvta_generic_to_shared(s);
    asm volatile("cp.async.cg.shared.global [%0], [%1], 16;\n" :: "r"(si), "l"(g));
}
__device__ __forceinline__ void cp_commit() {
    asm volatile("cp.async.commit_group;\n" ::);
}

// tf32 hi/lo split: f = hi + lo (+ ~2^-23 f)
__device__ __forceinline__ void tf32_split(float f, float& hi, float& lo) {
    uint32_t h, l;
    asm("cvt.rna.tf32.f32 %0, %1;" : "=r"(h) : "f"(f));
    float r = f - __uint_as_float(h);
    asm("cvt.rna.tf32.f32 %0, %1;" : "=r"(l) : "f"(r));
    hi = __uint_as_float(h);
    lo = __uint_as_float(l);
}
__device__ __forceinline__ float tf32_hi(float f) {
    uint32_t h;
    asm("cvt.rna.tf32.f32 %0, %1;" : "=r"(h) : "f"(f));
    return __uint_as_float(h);
}

__device__ __forceinline__ void mma8(float* d, const uint32_t* a, const uint32_t* b) {
    asm volatile(
        "mma.sync.aligned.m16n8k8.row.col.f32.tf32.tf32.f32 "
        "{%0,%1,%2,%3},{%4,%5,%6,%7},{%8,%9},{%0,%1,%2,%3};"
        : "+f"(d[0]), "+f"(d[1]), "+f"(d[2]), "+f"(d[3])
        : "r"(a[0]), "r"(a[1]), "r"(a[2]), "r"(a[3]), "r"(b[0]), "r"(b[1]));
}

__global__ void init_kernel() {
    int i = blockIdx.x * blockDim.x + threadIdx.x;
    if (i < BB * CC) g_scores[i] = 0.0f;
    if (i == 0) { g_sumsq_adj = 0.0; g_ent = 0.0; }
}

// natural elementwise split (float4 grid-stride), hi+lo
__global__ void nsplit_kernel(const float* __restrict__ in,
                              float* __restrict__ hi, float* __restrict__ lo, int n4) {
    for (int i = blockIdx.x * blockDim.x + threadIdx.x; i < n4;
         i += gridDim.x * blockDim.x) {
        float4 v = ((const float4*)in)[i];
        float4 h, l;
        tf32_split(v.x, h.x, l.x); tf32_split(v.y, h.y, l.y);
        tf32_split(v.z, h.z, l.z); tf32_split(v.w, h.w, l.w);
        ((float4*)hi)[i] = h;
        ((float4*)lo)[i] = l;
    }
}

// all six weight matrices, hi only; grid (64, 6)
__global__ void wsplit_kernel(const float* w0, const float* w1, const float* w2,
                              const float* w3, const float* w4, const float* w5) {
    const float* src[6] = {w0, w1, w2, w3, w4, w5};
    int w = blockIdx.y;
    int i = blockIdx.x * blockDim.x + threadIdx.x;        // 0..16383 (float4)
    float4 v = ((const float4*)src[w])[i];
    float4 h;
    h.x = tf32_hi(v.x); h.y = tf32_hi(v.y);
    h.z = tf32_hi(v.z); h.w = tf32_hi(v.w);
    ((float4*)(g_W_hi + w * 65536))[i] = h;
}

// adj pass: hi-only split + invdeg + sumsq; shuffle reductions (2 barriers)
__global__ void split_adj_kernel(const float* __restrict__ adj) {
    int b = blockIdx.y, n = blockIdx.x, t = threadIdx.x;
    int lane = t & 31, w = t >> 5;
    size_t o4 = (((size_t)b * NN_ + n) * NN_) / 4 + t;
    float4 v = ((const float4*)adj)[o4];
    float4 h;
    h.x = tf32_hi(v.x); h.y = tf32_hi(v.y);
    h.z = tf32_hi(v.z); h.w = tf32_hi(v.w);
    ((float4*)g_adjN_hi)[o4] = h;
    float rs = v.x + v.y + v.z + v.w;
    double ss = (double)v.x * v.x + (double)v.y * v.y
              + (double)v.z * v.z + (double)v.w * v.w;
    #pragma unroll
    for (int o = 16; o; o >>= 1) {
        rs += __shfl_xor_sync(0xffffffffu, rs, o);
        ss += __shfl_xor_sync(0xffffffffu, ss, o);
    }
    __shared__ float swr[8];
    __shared__ double swd[8];
    if (lane == 0) { swr[w] = rs; swd[w] = ss; }
    __syncthreads();
    if (t == 0) {
        float r = 0.f; double s = 0.0;
        #pragma unroll
        for (int i = 0; i < 8; i++) { r += swr[i]; s += swd[i]; }
        g_invdeg[b * NN_ + n] = 1.0f / fmaxf(r, 1.0f);
        atomicAdd(&g_sumsq_adj, s);
    }
}

// ---------------- pure-plane tensor-core GEMM (128x128x16, tf32 2x) -------------
// LOB=false: d += A_hi*B_hi + A_lo*B_hi   (lo plane on A side)
// LOB=true : d += A_hi*B_hi + A_hi*B_lo   (lo plane on B side)
// AMAJ=true : A planes natural [m][k], ldA = row stride ([128][20] smem)
// AMAJ=false: A planes k-major [k][m], ldA = k-row stride ([16][136] smem)
// B planes k-major [k][n] ([16][136] smem). 8 warps = 2(m) x 4(n).
#define GSMEM_B (2 * 7296 * 4)

template<bool AMAJ, bool LOB>
__global__ __launch_bounds__(256, 2) void gemm_tc(
    const float* __restrict__ Ahi, const float* __restrict__ Alo,
    const float* __restrict__ Bhi, const float* __restrict__ Blo,
    const float* __restrict__ A2hi, const float* __restrict__ A2lo,
    const float* __restrict__ B2hi, const float* __restrict__ B2lo,
    float* __restrict__ C, float* __restrict__ Chi, float* __restrict__ Clo,
    const float* __restrict__ bias, const float* __restrict__ rowmul,
    int ldA, int ldB, int Nn, int Kd,
    size_t sA, size_t sB, size_t sC, size_t sRm)
{
    constexpr int AP    = AMAJ ? 2560 : 2176;   // one A plane (floats)
    constexpr int NA    = LOB ? 1 : 2;
    constexpr int BOFF  = NA * AP;
    constexpr int STAGE = NA * AP + (LOB ? 2 : 1) * 2176;
    extern __shared__ float smem[];

    int bz = blockIdx.z;
    int bm = blockIdx.y * 128, bn = blockIdx.x * 128;
    int tid = threadIdx.x;
    int lane = tid & 31, wid = tid >> 5;
    int g = lane >> 2, tg = lane & 3;
    int mw = (wid & 1) * 64, nw = (wid >> 1) * 32;

    const float* A1h = Ahi + (size_t)bz * sA;
    const float* A1l = Alo ? Alo + (size_t)bz * sA : nullptr;
    const float* B1h = Bhi + (size_t)bz * sB;
    const float* B1l = Blo ? Blo + (size_t)bz * sB : nullptr;
    const float* A2h = A2hi ? A2hi + (size_t)bz * sA : nullptr;
    const float* A2l = A2lo ? A2lo + (size_t)bz * sA : nullptr;
    const float* B2h = A2hi ? B2hi + (size_t)bz * sB : nullptr;
    const float* B2l = B2lo ? B2lo + (size_t)bz * sB : nullptr;
    const int T1 = Kd / 16;
    const int T  = A2hi ? 2 * T1 : T1;

    auto issue = [&](int t, int buf) {
        const float *ah, *al, *bh, *bl; int k0;
        if (t < T1) { ah = A1h; al = A1l; bh = B1h; bl = B1l; k0 = t * 16; }
        else        { ah = A2h; al = A2l; bh = B2h; bl = B2l; k0 = (t - T1) * 16; }
        float* S = smem + buf * STAGE;
        if (AMAJ) {
            #pragma unroll
            for (int i = 0; i < 2; i++) {            // A [128][20] m-major
                int id = tid * 2 + i;
                int row = id >> 2, ch = (id & 3) * 4;
                size_t ga = (size_t)(bm + row) * ldA + k0 + ch;
                int so = row * 20 + ch;
                cp16(&S[so], ah + ga);
                if (!LOB) cp16(&S[AP + so], al + ga);
            }
        } else {
            #pragma unroll
            for (int i = 0; i < 2; i++) {            // A [16][136] k-major
                int id = tid * 2 + i;
                int r = id >> 5, c = (id & 31) * 4;
                size_t ga = (size_t)(k0 + r) * ldA + bm + c;
                int so = r * 136 + c;
                cp16(&S[so], ah + ga);
                if (!LOB) cp16(&S[AP + so], al + ga);
            }
        }
        #pragma unroll
        for (int i = 0; i < 2; i++) {                // B [16][136]
            int id = tid * 2 + i;
            int r = id >> 5, c = (id & 31) * 4;
            size_t gb = (size_t)(k0 + r) * ldB + bn + c;
            int so = r * 136 + c;
            cp16(&S[BOFF + so], bh + gb);
            if (LOB) cp16(&S[BOFF + 2176 + so], bl + gb);
        }
        cp_commit();
    };

    float d[4][4][4];
    #pragma unroll
    for (int i = 0; i < 4; i++)
        #pragma unroll
        for (int j = 0; j < 4; j++)
            #pragma unroll
            for (int q = 0; q < 4; q++) d[i][j][q] = 0.0f;

    issue(0, 0);
    issue(1, 1);

    for (int t = 0; t < T; t++) {
        if (t + 1 < T) asm volatile("cp.async.wait_group 1;\n" ::);
        else           asm volatile("cp.async.wait_group 0;\n" ::);
        __syncthreads();

        const float* S  = smem + (t & 1) * STAGE;
        const float* Ah = S;
        const float* Al = S + AP;                 // valid only if !LOB
        const float* Bh = S + BOFF;
        const float* Bl = S + BOFF + 2176;        // valid only if LOB

        #pragma unroll
        for (int ks = 0; ks < 16; ks += 8) {
            int kro = (ks + tg) * 136;
            uint32_t bh[4][2], bl4[4][2];
            #pragma unroll
            for (int nt = 0; nt < 4; nt++) {
                int o = kro + nw + nt * 8 + g;
                bh[nt][0] = __float_as_uint(Bh[o]);
                bh[nt][1] = __float_as_uint(Bh[o + 544]);
                if (LOB) {
                    bl4[nt][0] = __float_as_uint(Bl[o]);
                    bl4[nt][1] = __float_as_uint(Bl[o + 544]);
                }
            }
            #pragma unroll
            for (int mt = 0; mt < 4; mt++) {
                uint32_t ah[4], al4[4];
                if (AMAJ) {
                    int mo = (mw + mt * 16 + g) * 20 + ks + tg;
                    ah[0] = __float_as_uint(Ah[mo]);
                    ah[1] = __float_as_uint(Ah[mo + 160]);      // m+8
                    ah[2] = __float_as_uint(Ah[mo + 4]);        // k+4
                    ah[3] = __float_as_uint(Ah[mo + 164]);
                    if (!LOB) {
                        al4[0] = __float_as_uint(Al[mo]);
                        al4[1] = __float_as_uint(Al[mo + 160]);
                        al4[2] = __float_as_uint(Al[mo + 4]);
                        al4[3] = __float_as_uint(Al[mo + 164]);
                    }
                } else {
                    int o = kro + mw + mt * 16 + g;
                    ah[0] = __float_as_uint(Ah[o]);
                    ah[1] = __float_as_uint(Ah[o + 8]);
                    ah[2] = __float_as_uint(Ah[o + 544]);
                    ah[3] = __float_as_uint(Ah[o + 552]);
                    if (!LOB) {
                        al4[0] = __float_as_uint(Al[o]);
                        al4[1] = __float_as_uint(Al[o + 8]);
                        al4[2] = __float_as_uint(Al[o + 544]);
                        al4[3] = __float_as_uint(Al[o + 552]);
                    }
                }
                #pragma unroll
                for (int nt = 0; nt < 4; nt++) {
                    mma8(d[mt][nt], ah, bh[nt]);
                    if (LOB) mma8(d[mt][nt], ah, bl4[nt]);
                    else     mma8(d[mt][nt], al4, bh[nt]);
                }
            }
        }
        __syncthreads();
        if (t + 2 < T) issue(t + 2, t & 1);
    }

    // epilogue: optional rowmul, bias; fp32 C; hi plane if Chi; lo plane if Clo
    #pragma unroll
    for (int mt = 0; mt < 4; mt++) {
        int r0 = bm + mw + mt * 16 + g;
        float rm0 = 1.0f, rm8 = 1.0f;
        if (rowmul) {
            rm0 = rowmul[bz * sRm + r0];
            rm8 = rowmul[bz * sRm + r0 + 8];
        }
        #pragma unroll
        for (int nt = 0; nt < 4; nt++) {
            int c = bn + nw + nt * 8 + tg * 2;
            float2 v0, v8;
            v0.x = d[mt][nt][0]; v0.y = d[mt][nt][1];
            v8.x = d[mt][nt][2]; v8.y = d[mt][nt][3];
            if (rowmul) { v0.x *= rm0; v0.y *= rm0; v8.x *= rm8; v8.y *= rm8; }
            if (bias) {
                float2 bb = *(const float2*)&bias[c];
                v0.x += bb.x; v0.y += bb.y; v8.x += bb.x; v8.y += bb.y;
            }
            size_t o0 = (size_t)bz * sC + (size_t)r0 * Nn + c;
            size_t o8 = o0 + (size_t)8 * Nn;
            if (C) {
                *(float2*)&C[o0] = v0;
                *(float2*)&C[o8] = v8;
            }
            if (Chi) {
                float2 h0, l0, h8, l8;
                tf32_split(v0.x, h0.x, l0.x); tf32_split(v0.y, h0.y, l0.y);
                tf32_split(v8.x, h8.x, l8.x); tf32_split(v8.y, h8.y, l8.y);
                *(float2*)&Chi[o0] = h0; *(float2*)&Chi[o8] = h8;
                if (Clo) { *(float2*)&Clo[o0] = l0; *(float2*)&Clo[o8] = l8; }
            }
        }
    }
}

// normrelu + split, natural: pre[row][256] -> h hi/lo planes natural
__global__ void normrelu_split_kernel() {
    size_t row = blockIdx.x;
    int t = threadIdx.x;
    float v = g_pre[row * HH + t];
    __shared__ float sm[256];
    sm[t] = v * v; __syncthreads();
    for (int o = 128; o > 0; o >>= 1) {
        if (t < o) sm[t] += sm[t + o];
        __syncthreads();
    }
    float rn = 1.0f / fmaxf(sqrtf(sm[0]), 1e-12f);
    float r = fmaxf(v, 0.0f) * rn;
    float h, l;
    tf32_split(r, h, l);
    g_h_hi[row * HH + t] = h;
    g_h_lo[row * HH + t] = l;
}

// softmax over last dim (256), in place
__global__ void softmax_kernel(float* __restrict__ s) {
    size_t row = blockIdx.x;
    float* r = s + row * CC;
    float v = r[threadIdx.x];
    __shared__ float sm[256];
    sm[threadIdx.x] = v; __syncthreads();
    for (int o = 128; o > 0; o >>= 1) {
        if (threadIdx.x < o) sm[threadIdx.x] = fmaxf(sm[threadIdx.x], sm[threadIdx.x + o]);
        __syncthreads();
    }
    float mx = sm[0]; __syncthreads();
    float e = expf(v - mx);
    sm[threadIdx.x] = e; __syncthreads();
    for (int o = 128; o > 0; o >>= 1) {
        if (threadIdx.x < o) sm[threadIdx.x] += sm[threadIdx.x + o];
        __syncthreads();
    }
    r[threadIdx.x] = e / sm[0];
}

// scores[b,c] = sum_n s[b,n,c]   grid: (8, B)
__global__ void colsum_kernel(const float* __restrict__ s) {
    int b = blockIdx.y;
    const float* base = s + ((size_t)b * NN_ + (size_t)blockIdx.x * 128) * CC;
    float acc = 0.f;
    for (int r = 0; r < 128; r++) acc += base[(size_t)r * CC + threadIdx.x];
    atomicAdd(&g_scores[b * CC + threadIdx.x], acc);
}

__global__ void topk_kernel() {
    int b = blockIdx.x, t = threadIdx.x;
    __shared__ float sm[256];
    sm[t] = g_scores[b * CC + t]; __syncthreads();
    float v = sm[t];
    int cnt = 0;
    for (int j = 0; j < CC; j++) {
        float w = sm[j];
        cnt += (w > v) || (w == v && j < t);
    }
    if (cnt == KTOP - 1) g_thresh[b] = v;
}

// s *= gate; write s fp32 + sN hi/lo planes; entropy   grid: (8, B)
__global__ void gate_split_kernel(float* __restrict__ s) {
    int b = blockIdx.y, t = threadIdx.x;
    float xg = (g_scores[b * CC + t] - g_thresh[b]) / TEMPR;
    float gt;
    if (xg >= 0.f) gt = 1.0f / (1.0f + expf(-xg));
    else { float ex = expf(xg); gt = ex / (1.0f + ex); }
    size_t base = ((size_t)b * NN_ + (size_t)blockIdx.x * 128) * CC;
    double e = 0.0;
    for (int r = 0; r < 128; r++) {
        size_t idx = base + (size_t)r * CC + t;
        float v = s[idx] * gt;
        s[idx] = v;
        float h, l;
        tf32_split(v, h, l);
        g_sN_hi[idx] = h; g_sN_lo[idx] = l;
        e += (double)(-v * logf(v + 1e-15f));
    }
    __shared__ double sm[256];
    double tot = block_red_d(e, sm);
    if (t == 0) atomicAdd(&g_ent, tot);
}

// per-batch traces / frobenius sums over [C,C] mats
__global__ void batchred_kernel(const float* __restrict__ adjp) {
    int b = blockIdx.x, t = threadIdx.x;
    const float* P = adjp  + (size_t)b * CC * CC;
    const float* G = g_sts + (size_t)b * CC * CC;
    const float* U = g_U   + (size_t)b * CC * CC;
    const float* V = g_V   + (size_t)b * CC * CC;
    double trA = 0, ssA = 0, trG = 0, ssG = 0, duv = 0;
    for (int i = t; i < CC * CC; i += 256) {
        float p = P[i]; ssA += (double)p * p;
        float g = G[i]; ssG += (double)g * g;
        duv += (double)U[i] * (double)V[i];
        if (i % (CC + 1) == 0) { trA += p; trG += g; }
    }
    __shared__ double sm[256];
    double r;
    r = block_red_d(trA, sm); if (t == 0) g_trA[b] = r;
    r = block_red_d(ssA, sm); if (t == 0) g_ssA[b] = r;
    r = block_red_d(trG, sm); if (t == 0) g_trG[b] = r;
    r = block_red_d(ssG, sm); if (t == 0) g_ssG[b] = r;
    r = block_red_d(duv, sm); if (t == 0) g_dotUV[b] = r;
}

__global__ void final_kernel(float* __restrict__ o) {
    double linksq = g_sumsq_adj, reconsq = g_sumsq_adj, clusum = 0.0;
    for (int b = 0; b < BB; b++) {
        linksq  += -2.0 * g_trA[b] + g_ssG[b];
        reconsq += -2.0 * g_ssA[b] + g_dotUV[b];
        double nrm = sqrt(g_ssG[b]); if (nrm < 1e-12) nrm = 1e-12;
        double t1 = g_ssG[b] / (nrm * nrm);
        double cb = t1 - 2.0 * g_trG[b] / (nrm * 16.0) + 1.0;   // sqrt(C)=16
        clusum += sqrt(cb > 0.0 ? cb : 0.0);
    }
    double sz = (double)BB * NN_ * NN_;
    o[0] = (float)(sqrt(linksq  > 0.0 ? linksq  : 0.0) / sz);  // link
    o[1] = (float)(g_ent / ((double)BB * NN_));                // ent
    o[2] = (float)(clusum / BB);                               // clu
    o[3] = (float)(sqrt(reconsq > 0.0 ? reconsq : 0.0) / sz);  // recon
}

// ---------------- launch ----------------
#define SYM(p, s) cudaGetSymbolAddress((void**)&p, s)

extern "C" void kernel_launch(void* const* d_in, const int* in_sizes, int n_in,
                              void* d_out, int out_size) {
    const float* x    = (const float*)d_in[0];
    const float* adj  = (const float*)d_in[1];
    const float* br_p = (const float*)d_in[3];
    const float* bl_p = (const float*)d_in[6];
    const float* br_e = (const float*)d_in[8];
    const float* bl_e = (const float*)d_in[11];

    float* out       = (float*)d_out;
    float* out_xp    = out;                         // [B,C,E]
    float* out_adjp  = out + 2097152;               // [B,C,C]
    float* out_s     = out + 4194304;               // [B,N,C]
    float* out_scal  = out + 12582912;              // link, ent, clu, recon
    float* out_nodex = out + 12582916;              // [B,N,E]

    float *adjNh, *xNh, *xNl, *aggNh, *aggNl, *hh, *hl;
    float *ndxh, *sNh, *sNl, *aTsh, *Wh;
    float *apNh, *apNl, *stsNh, *pre, *sts, *U, *V, *invdeg;
    SYM(adjNh, g_adjN_hi);
    SYM(xNh, g_xN_hi); SYM(xNl, g_xN_lo);
    SYM(aggNh, g_aggN_hi); SYM(aggNl, g_aggN_lo);
    SYM(hh, g_h_hi); SYM(hl, g_h_lo);
    SYM(ndxh, g_ndx_hi);
    SYM(sNh, g_sN_hi); SYM(sNl, g_sN_lo);
    SYM(aTsh, g_aTs_hi);
    SYM(Wh, g_W_hi);
    SYM(apNh, g_apN_hi); SYM(apNl, g_apN_lo);
    SYM(stsNh, g_stsN_hi);
    SYM(pre, g_pre); SYM(sts, g_sts); SYM(U, g_U); SYM(V, g_V);
    SYM(invdeg, g_invdeg);

    cudaFuncSetAttribute(gemm_tc<true, false>,  cudaFuncAttributeMaxDynamicSharedMemorySize, GSMEM_B);
    cudaFuncSetAttribute(gemm_tc<true, true>,   cudaFuncAttributeMaxDynamicSharedMemorySize, GSMEM_B);
    cudaFuncSetAttribute(gemm_tc<false, false>, cudaFuncAttributeMaxDynamicSharedMemorySize, GSMEM_B);
    cudaFuncSetAttribute(gemm_tc<false, true>,  cudaFuncAttributeMaxDynamicSharedMemorySize, GSMEM_B);

    init_kernel<<<32, 256>>>();

    // input splits
    nsplit_kernel<<<4096, 256>>>(x, xNh, xNl, 2097152);
    wsplit_kernel<<<dim3(64, 6), 256>>>(
        (const float*)d_in[2], (const float*)d_in[4], (const float*)d_in[5],
        (const float*)d_in[7], (const float*)d_in[9], (const float*)d_in[10]);
    split_adj_kernel<<<dim3(NN_, BB), 256>>>(adj);

    // agg = (adj @ x) * invdeg(row)   LOB: adj truncated, x hi+lo on B
    gemm_tc<true, true><<<dim3(2, 8, BB), 256, GSMEM_B>>>(
        adjNh, nullptr, xNh, xNl, nullptr, nullptr, nullptr, nullptr,
        nullptr, aggNh, aggNl, nullptr, invdeg,
        1024, 256, 256, 1024,
        (size_t)NN_ * NN_, (size_t)NN_ * DD, (size_t)NN_ * DD, NN_);

    // ---- embed branch ----
    gemm_tc<true, false><<<dim3(2, 256, 1), 256, GSMEM_B>>>(   // pre = agg@Wr_e + x@Wo_e + br_e
        aggNh, aggNl, Wh + 3 * 65536, nullptr,
        xNh, xNl, Wh + 4 * 65536, nullptr,
        pre, nullptr, nullptr, br_e, nullptr,
        256, 256, 256, 256, 0, 0, 0, 0);
    normrelu_split_kernel<<<BB * NN_, 256>>>();
    gemm_tc<true, false><<<dim3(2, 256, 1), 256, GSMEM_B>>>(   // nodex = h@Wl_e + bl_e
        hh, hl, Wh + 5 * 65536, nullptr,
        nullptr, nullptr, nullptr, nullptr,
        out_nodex, ndxh, nullptr, bl_e, nullptr,
        256, 256, 256, 256, 0, 0, 0, 0);

    // ---- pool branch ----
    gemm_tc<true, false><<<dim3(2, 256, 1), 256, GSMEM_B>>>(   // pre = agg@Wr_p + x@Wo_p + br_p
        aggNh, aggNl, Wh + 0 * 65536, nullptr,
        xNh, xNl, Wh + 1 * 65536, nullptr,
        pre, nullptr, nullptr, br_p, nullptr,
        256, 256, 256, 256, 0, 0, 0, 0);
    normrelu_split_kernel<<<BB * NN_, 256>>>();
    gemm_tc<true, false><<<dim3(2, 256, 1), 256, GSMEM_B>>>(   // logits = h@Wl_p + bl_p
        hh, hl, Wh + 2 * 65536, nullptr,
        nullptr, nullptr, nullptr, nullptr,
        out_s, nullptr, nullptr, bl_p, nullptr,
        256, 256, 256, 256, 0, 0, 0, 0);

    // softmax, scores, top-k gate (+entropy, +s planes)
    softmax_kernel<<<BB * NN_, 256>>>(out_s);
    colsum_kernel<<<dim3(8, BB), 256>>>(out_s);
    topk_kernel<<<BB, 256>>>();
    gate_split_kernel<<<dim3(8, BB), 256>>>(out_s);

    // xp = s^T @ nodex    (A = sN k-major, lo on A; ndx hi only)
    gemm_tc<false, false><<<dim3(2, 2, BB), 256, GSMEM_B>>>(
        sNh, sNl, ndxh, nullptr, nullptr, nullptr, nullptr, nullptr,
        out_xp, nullptr, nullptr, nullptr, nullptr,
        256, 256, 256, 1024,
        (size_t)NN_ * CC, (size_t)NN_ * EE, (size_t)CC * EE, 0);

    // aTs = adj^T @ s     (A = adjN k-major hi only; s hi+lo on B)
    gemm_tc<false, true><<<dim3(2, 8, BB), 256, GSMEM_B>>>(
        adjNh, nullptr, sNh, sNl, nullptr, nullptr, nullptr, nullptr,
        nullptr, aTsh, nullptr, nullptr, nullptr,
        1024, 256, 256, 1024,
        (size_t)NN_ * NN_, (size_t)NN_ * CC, (size_t)NN_ * CC, 0);

    // adj_p = aTs^T @ s   (A = aTs hi only; s hi+lo on B)
    gemm_tc<false, true><<<dim3(2, 2, BB), 256, GSMEM_B>>>(
        aTsh, nullptr, sNh, sNl, nullptr, nullptr, nullptr, nullptr,
        out_adjp, apNh, apNl, nullptr, nullptr,
        256, 256, 256, 1024,
        (size_t)NN_ * CC, (size_t)NN_ * CC, (size_t)CC * CC, 0);

    // sts = s^T @ s       (A = sN hi+lo; B = sN hi)
    gemm_tc<false, false><<<dim3(2, 2, BB), 256, GSMEM_B>>>(
        sNh, sNl, sNh, nullptr, nullptr, nullptr, nullptr, nullptr,
        sts, stsNh, nullptr, nullptr, nullptr,
        256, 256, 256, 1024,
        (size_t)NN_ * CC, (size_t)NN_ * CC, (size_t)CC * CC, 0);

    // U = adjp @ sts  (A = apN hi+lo; B = sts hi)
    gemm_tc<true, false><<<dim3(2, 2, BB), 256, GSMEM_B>>>(
        apNh, apNl, stsNh, nullptr, nullptr, nullptr, nullptr, nullptr,
        U, nullptr, nullptr, nullptr, nullptr,
        256, 256, 256, 256,
        (size_t)CC * CC, (size_t)CC * CC, (size_t)CC * CC, 0);
    // V = sts @ adjp  (A = sts hi only; B = apN hi+lo)
    gemm_tc<true, true><<<dim3(2, 2, BB), 256, GSMEM_B>>>(
        stsNh, nullptr, apNh, apNl, nullptr, nullptr, nullptr, nullptr,
        V, nullptr, nullptr, nullptr, nullptr,
        256, 256, 256, 256,
        (size_t)CC * CC, (size_t)CC * CC, (size_t)CC * CC, 0);

    // scalar losses
    batchred_kernel<<<BB, 256>>>(out_adjp);
    final_kernel<<<1, 1>>>(out_scal);
}

// round 17
// speedup vs baseline: 1.9505x; 1.0696x over previous
#include <cuda_runtime.h>
#include <math.h>
#include <stdint.h>

// Problem constants
#define BB   32
#define NN_  1024
#define DD   256
#define HH   256
#define EE   256
#define CC   256
#define KTOP 128
#define TEMPR 0.1f

// ---------------- scratch (device globals; no allocation allowed) ----------------
// tf32 planes, natural orientation. lo planes only where consumed.
__device__ float g_adjN_hi[33554432];                        // [b][n][m]
__device__ float g_xN_hi[8388608],   g_xN_lo[8388608];       // [b][n][d]
__device__ float g_aggN_hi[8388608], g_aggN_lo[8388608];     // [b][n][d]
__device__ float g_h_hi[8388608],    g_h_lo[8388608];        // [node][h]
__device__ float g_ndx_hi[8388608];                          // [node][e]
__device__ float g_sN_hi[8388608],   g_sN_lo[8388608];       // [b][n][c]
__device__ float g_aTs_hi[8388608];                          // [b][m][c]
__device__ float g_W_hi[6 * 65536];                          // 0Wr_p 1Wo_p 2Wl_p 3Wr_e 4Wo_e 5Wl_e
__device__ float g_apN_hi[2097152],  g_apN_lo[2097152];      // adj_p planes
__device__ float g_stsN_hi[2097152];                         // sts plane
__device__ float g_pre[8388608];
__device__ float g_sts[2097152], g_U[2097152], g_V[2097152];
__device__ float g_invdeg[BB * NN_];
__device__ float g_scores[BB * CC];
__device__ float g_thresh[BB];
__device__ double g_sumsq_adj;
__device__ double g_ent;
__device__ double g_trA[BB], g_ssA[BB], g_trG[BB], g_ssG[BB], g_dotUV[BB];

// ---------------- helpers ----------------
__device__ __forceinline__ double block_red_d(double v, double* sm) {
    int t = threadIdx.x;
    sm[t] = v; __syncthreads();
    for (int o = 128; o > 0; o >>= 1) {
        if (t < o) sm[t] += sm[t + o];
        __syncthreads();
    }
    double r = sm[0]; __syncthreads();
    return r;
}

__device__ __forceinline__ void cp16(void* s, const void* g) {
    uint32_t si = (uint32_t)__cvta_generic_to_shared(s);
    asm volatile("cp.async.cg.shared.global [%0], [%1], 16;\n" :: "r"(si), "l"(g));
}
__device__ __forceinline__ void cp_commit() {
    asm volatile("cp.async.commit_group;\n" ::);
}

// tf32 hi/lo split: f = hi + lo (+ ~2^-23 f)
__device__ __forceinline__ void tf32_split(float f, float& hi, float& lo) {
    uint32_t h, l;
    asm("cvt.rna.tf32.f32 %0, %1;" : "=r"(h) : "f"(f));
    float r = f - __uint_as_float(h);
    asm("cvt.rna.tf32.f32 %0, %1;" : "=r"(l) : "f"(r));
    hi = __uint_as_float(h);
    lo = __uint_as_float(l);
}
__device__ __forceinline__ float tf32_hi(float f) {
    uint32_t h;
    asm("cvt.rna.tf32.f32 %0, %1;" : "=r"(h) : "f"(f));
    return __uint_as_float(h);
}

__device__ __forceinline__ void mma8(float* d, const uint32_t* a, const uint32_t* b) {
    asm volatile(
        "mma.sync.aligned.m16n8k8.row.col.f32.tf32.tf32.f32 "
        "{%0,%1,%2,%3},{%4,%5,%6,%7},{%8,%9},{%0,%1,%2,%3};"
        : "+f"(d[0]), "+f"(d[1]), "+f"(d[2]), "+f"(d[3])
        : "r"(a[0]), "r"(a[1]), "r"(a[2]), "r"(a[3]), "r"(b[0]), "r"(b[1]));
}

__global__ void init_kernel() {
    int i = blockIdx.x * blockDim.x + threadIdx.x;
    if (i < BB * CC) g_scores[i] = 0.0f;
    if (i == 0) { g_sumsq_adj = 0.0; g_ent = 0.0; }
}

// natural elementwise split (float4 grid-stride), hi+lo
__global__ void nsplit_kernel(const float* __restrict__ in,
                              float* __restrict__ hi, float* __restrict__ lo, int n4) {
    for (int i = blockIdx.x * blockDim.x + threadIdx.x; i < n4;
         i += gridDim.x * blockDim.x) {
        float4 v = ((const float4*)in)[i];
        float4 h, l;
        tf32_split(v.x, h.x, l.x); tf32_split(v.y, h.y, l.y);
        tf32_split(v.z, h.z, l.z); tf32_split(v.w, h.w, l.w);
        ((float4*)hi)[i] = h;
        ((float4*)lo)[i] = l;
    }
}

// all six weight matrices, hi only; grid (64, 6)
__global__ void wsplit_kernel(const float* w0, const float* w1, const float* w2,
                              const float* w3, const float* w4, const float* w5) {
    const float* src[6] = {w0, w1, w2, w3, w4, w5};
    int w = blockIdx.y;
    int i = blockIdx.x * blockDim.x + threadIdx.x;        // 0..16383 (float4)
    float4 v = ((const float4*)src[w])[i];
    float4 h;
    h.x = tf32_hi(v.x); h.y = tf32_hi(v.y);
    h.z = tf32_hi(v.z); h.w = tf32_hi(v.w);
    ((float4*)(g_W_hi + w * 65536))[i] = h;
}

// adj pass: warp-per-row (MLP=8). hi split + invdeg + sumsq.
// grid: BB*NN_/8 blocks of 256 (8 warps, one row each)
__global__ void split_adj_kernel(const float* __restrict__ adj) {
    int w = threadIdx.x >> 5, lane = threadIdx.x & 31;
    size_t row = (size_t)blockIdx.x * 8 + w;              // 0..32767
    const float4* src = (const float4*)(adj + row * NN_);
    float4* dst = (float4*)(g_adjN_hi + row * NN_);
    float rs = 0.f;
    double ss = 0.0;
    #pragma unroll
    for (int i = 0; i < 8; i++) {
        float4 v = src[lane + 32 * i];
        float4 h;
        h.x = tf32_hi(v.x); h.y = tf32_hi(v.y);
        h.z = tf32_hi(v.z); h.w = tf32_hi(v.w);
        dst[lane + 32 * i] = h;
        rs += v.x + v.y + v.z + v.w;
        ss += (double)v.x * v.x + (double)v.y * v.y
            + (double)v.z * v.z + (double)v.w * v.w;
    }
    #pragma unroll
    for (int o = 16; o; o >>= 1) {
        rs += __shfl_xor_sync(0xffffffffu, rs, o);
        ss += __shfl_xor_sync(0xffffffffu, ss, o);
    }
    if (lane == 0) {
        g_invdeg[row] = 1.0f / fmaxf(rs, 1.0f);
        atomicAdd(&g_sumsq_adj, ss);
    }
}

// ---------------- pure-plane tensor-core GEMM (128x128x16, tf32 2x) -------------
// LOB=false: d += A_hi*B_hi + A_lo*B_hi   (lo plane on A side)
// LOB=true : d += A_hi*B_hi + A_hi*B_lo   (lo plane on B side)
// AMAJ=true : A planes natural [m][k], ldA = row stride ([128][20] smem)
// AMAJ=false: A planes k-major [k][m], ldA = k-row stride ([16][136] smem)
// B planes k-major [k][n] ([16][136] smem). 8 warps = 2(m) x 4(n).
#define GSMEM_B (2 * 7296 * 4)

template<bool AMAJ, bool LOB>
__global__ __launch_bounds__(256, 2) void gemm_tc(
    const float* __restrict__ Ahi, const float* __restrict__ Alo,
    const float* __restrict__ Bhi, const float* __restrict__ Blo,
    const float* __restrict__ A2hi, const float* __restrict__ A2lo,
    const float* __restrict__ B2hi, const float* __restrict__ B2lo,
    float* __restrict__ C, float* __restrict__ Chi, float* __restrict__ Clo,
    const float* __restrict__ bias, const float* __restrict__ rowmul,
    int ldA, int ldB, int Nn, int Kd,
    size_t sA, size_t sB, size_t sC, size_t sRm)
{
    constexpr int AP    = AMAJ ? 2560 : 2176;   // one A plane (floats)
    constexpr int NA    = LOB ? 1 : 2;
    constexpr int BOFF  = NA * AP;
    constexpr int STAGE = NA * AP + (LOB ? 2 : 1) * 2176;
    extern __shared__ float smem[];

    int bz = blockIdx.z;
    int bm = blockIdx.y * 128, bn = blockIdx.x * 128;
    int tid = threadIdx.x;
    int lane = tid & 31, wid = tid >> 5;
    int g = lane >> 2, tg = lane & 3;
    int mw = (wid & 1) * 64, nw = (wid >> 1) * 32;

    const float* A1h = Ahi + (size_t)bz * sA;
    const float* A1l = Alo ? Alo + (size_t)bz * sA : nullptr;
    const float* B1h = Bhi + (size_t)bz * sB;
    const float* B1l = Blo ? Blo + (size_t)bz * sB : nullptr;
    const float* A2h = A2hi ? A2hi + (size_t)bz * sA : nullptr;
    const float* A2l = A2lo ? A2lo + (size_t)bz * sA : nullptr;
    const float* B2h = A2hi ? B2hi + (size_t)bz * sB : nullptr;
    const float* B2l = B2lo ? B2lo + (size_t)bz * sB : nullptr;
    const int T1 = Kd / 16;
    const int T  = A2hi ? 2 * T1 : T1;

    auto issue = [&](int t, int buf) {
        const float *ah, *al, *bh, *bl; int k0;
        if (t < T1) { ah = A1h; al = A1l; bh = B1h; bl = B1l; k0 = t * 16; }
        else        { ah = A2h; al = A2l; bh = B2h; bl = B2l; k0 = (t - T1) * 16; }
        float* S = smem + buf * STAGE;
        if (AMAJ) {
            #pragma unroll
            for (int i = 0; i < 2; i++) {            // A [128][20] m-major
                int id = tid * 2 + i;
                int row = id >> 2, ch = (id & 3) * 4;
                size_t ga = (size_t)(bm + row) * ldA + k0 + ch;
                int so = row * 20 + ch;
                cp16(&S[so], ah + ga);
                if (!LOB) cp16(&S[AP + so], al + ga);
            }
        } else {
            #pragma unroll
            for (int i = 0; i < 2; i++) {            // A [16][136] k-major
                int id = tid * 2 + i;
                int r = id >> 5, c = (id & 31) * 4;
                size_t ga = (size_t)(k0 + r) * ldA + bm + c;
                int so = r * 136 + c;
                cp16(&S[so], ah + ga);
                if (!LOB) cp16(&S[AP + so], al + ga);
            }
        }
        #pragma unroll
        for (int i = 0; i < 2; i++) {                // B [16][136]
            int id = tid * 2 + i;
            int r = id >> 5, c = (id & 31) * 4;
            size_t gb = (size_t)(k0 + r) * ldB + bn + c;
            int so = r * 136 + c;
            cp16(&S[BOFF + so], bh + gb);
            if (LOB) cp16(&S[BOFF + 2176 + so], bl + gb);
        }
        cp_commit();
    };

    float d[4][4][4];
    #pragma unroll
    for (int i = 0; i < 4; i++)
        #pragma unroll
        for (int j = 0; j < 4; j++)
            #pragma unroll
            for (int q = 0; q < 4; q++) d[i][j][q] = 0.0f;

    issue(0, 0);
    issue(1, 1);

    for (int t = 0; t < T; t++) {
        if (t + 1 < T) asm volatile("cp.async.wait_group 1;\n" ::);
        else           asm volatile("cp.async.wait_group 0;\n" ::);
        __syncthreads();

        const float* S  = smem + (t & 1) * STAGE;
        const float* Ah = S;
        const float* Al = S + AP;                 // valid only if !LOB
        const float* Bh = S + BOFF;
        const float* Bl = S + BOFF + 2176;        // valid only if LOB

        #pragma unroll
        for (int ks = 0; ks < 16; ks += 8) {
            int kro = (ks + tg) * 136;
            uint32_t bh[4][2], bl4[4][2];
            #pragma unroll
            for (int nt = 0; nt < 4; nt++) {
                int o = kro + nw + nt * 8 + g;
                bh[nt][0] = __float_as_uint(Bh[o]);
                bh[nt][1] = __float_as_uint(Bh[o + 544]);
                if (LOB) {
                    bl4[nt][0] = __float_as_uint(Bl[o]);
                    bl4[nt][1] = __float_as_uint(Bl[o + 544]);
                }
            }
            #pragma unroll
            for (int mt = 0; mt < 4; mt++) {
                uint32_t ah[4], al4[4];
                if (AMAJ) {
                    int mo = (mw + mt * 16 + g) * 20 + ks + tg;
                    ah[0] = __float_as_uint(Ah[mo]);
                    ah[1] = __float_as_uint(Ah[mo + 160]);      // m+8
                    ah[2] = __float_as_uint(Ah[mo + 4]);        // k+4
                    ah[3] = __float_as_uint(Ah[mo + 164]);
                    if (!LOB) {
                        al4[0] = __float_as_uint(Al[mo]);
                        al4[1] = __float_as_uint(Al[mo + 160]);
                        al4[2] = __float_as_uint(Al[mo + 4]);
                        al4[3] = __float_as_uint(Al[mo + 164]);
                    }
                } else {
                    int o = kro + mw + mt * 16 + g;
                    ah[0] = __float_as_uint(Ah[o]);
                    ah[1] = __float_as_uint(Ah[o + 8]);
                    ah[2] = __float_as_uint(Ah[o + 544]);
                    ah[3] = __float_as_uint(Ah[o + 552]);
                    if (!LOB) {
                        al4[0] = __float_as_uint(Al[o]);
                        al4[1] = __float_as_uint(Al[o + 8]);
                        al4[2] = __float_as_uint(Al[o + 544]);
                        al4[3] = __float_as_uint(Al[o + 552]);
                    }
                }
                #pragma unroll
                for (int nt = 0; nt < 4; nt++) {
                    mma8(d[mt][nt], ah, bh[nt]);
                    if (LOB) mma8(d[mt][nt], ah, bl4[nt]);
                    else     mma8(d[mt][nt], al4, bh[nt]);
                }
            }
        }
        __syncthreads();
        if (t + 2 < T) issue(t + 2, t & 1);
    }

    // epilogue: optional rowmul, bias; fp32 C; hi plane if Chi; lo plane if Clo
    #pragma unroll
    for (int mt = 0; mt < 4; mt++) {
        int r0 = bm + mw + mt * 16 + g;
        float rm0 = 1.0f, rm8 = 1.0f;
        if (rowmul) {
            rm0 = rowmul[bz * sRm + r0];
            rm8 = rowmul[bz * sRm + r0 + 8];
        }
        #pragma unroll
        for (int nt = 0; nt < 4; nt++) {
            int c = bn + nw + nt * 8 + tg * 2;
            float2 v0, v8;
            v0.x = d[mt][nt][0]; v0.y = d[mt][nt][1];
            v8.x = d[mt][nt][2]; v8.y = d[mt][nt][3];
            if (rowmul) { v0.x *= rm0; v0.y *= rm0; v8.x *= rm8; v8.y *= rm8; }
            if (bias) {
                float2 bb = *(const float2*)&bias[c];
                v0.x += bb.x; v0.y += bb.y; v8.x += bb.x; v8.y += bb.y;
            }
            size_t o0 = (size_t)bz * sC + (size_t)r0 * Nn + c;
            size_t o8 = o0 + (size_t)8 * Nn;
            if (C) {
                *(float2*)&C[o0] = v0;
                *(float2*)&C[o8] = v8;
            }
            if (Chi) {
                float2 h0, l0, h8, l8;
                tf32_split(v0.x, h0.x, l0.x); tf32_split(v0.y, h0.y, l0.y);
                tf32_split(v8.x, h8.x, l8.x); tf32_split(v8.y, h8.y, l8.y);
                *(float2*)&Chi[o0] = h0; *(float2*)&Chi[o8] = h8;
                if (Clo) { *(float2*)&Clo[o0] = l0; *(float2*)&Clo[o8] = l8; }
            }
        }
    }
}

// normrelu + split, natural: pre[row][256] -> h hi/lo planes (shuffle reduce)
__global__ void normrelu_split_kernel() {
    size_t row = blockIdx.x;
    int t = threadIdx.x, lane = t & 31, w = t >> 5;
    float v = g_pre[row * HH + t];
    float sq = v * v;
    #pragma unroll
    for (int o = 16; o; o >>= 1) sq += __shfl_xor_sync(0xffffffffu, sq, o);
    __shared__ float sw[8];
    if (lane == 0) sw[w] = sq;
    __syncthreads();
    float tot = sw[0] + sw[1] + sw[2] + sw[3] + sw[4] + sw[5] + sw[6] + sw[7];
    float rn = 1.0f / fmaxf(sqrtf(tot), 1e-12f);
    float r = fmaxf(v, 0.0f) * rn;
    float h, l;
    tf32_split(r, h, l);
    g_h_hi[row * HH + t] = h;
    g_h_lo[row * HH + t] = l;
}

// softmax over last dim (256), in place (shuffle reduce)
__global__ void softmax_kernel(float* __restrict__ s) {
    size_t row = blockIdx.x;
    float* r = s + row * CC;
    int t = threadIdx.x, lane = t & 31, w = t >> 5;
    float v = r[t];
    float m = v;
    #pragma unroll
    for (int o = 16; o; o >>= 1) m = fmaxf(m, __shfl_xor_sync(0xffffffffu, m, o));
    __shared__ float swm[8], sws[8];
    if (lane == 0) swm[w] = m;
    __syncthreads();
    float mx = fmaxf(fmaxf(fmaxf(swm[0], swm[1]), fmaxf(swm[2], swm[3])),
                     fmaxf(fmaxf(swm[4], swm[5]), fmaxf(swm[6], swm[7])));
    float e = expf(v - mx);
    float sum = e;
    #pragma unroll
    for (int o = 16; o; o >>= 1) sum += __shfl_xor_sync(0xffffffffu, sum, o);
    if (lane == 0) sws[w] = sum;
    __syncthreads();
    float tot = sws[0] + sws[1] + sws[2] + sws[3] + sws[4] + sws[5] + sws[6] + sws[7];
    r[t] = e / tot;
}

// scores[b,c] = sum_n s[b,n,c]   grid: (8, B)
__global__ void colsum_kernel(const float* __restrict__ s) {
    int b = blockIdx.y;
    const float* base = s + ((size_t)b * NN_ + (size_t)blockIdx.x * 128) * CC;
    float acc = 0.f;
    for (int r = 0; r < 128; r++) acc += base[(size_t)r * CC + threadIdx.x];
    atomicAdd(&g_scores[b * CC + threadIdx.x], acc);
}

__global__ void topk_kernel() {
    int b = blockIdx.x, t = threadIdx.x;
    __shared__ float sm[256];
    sm[t] = g_scores[b * CC + t]; __syncthreads();
    float v = sm[t];
    int cnt = 0;
    for (int j = 0; j < CC; j++) {
        float w = sm[j];
        cnt += (w > v) || (w == v && j < t);
    }
    if (cnt == KTOP - 1) g_thresh[b] = v;
}

// s *= gate; write s fp32 + sN hi/lo planes; entropy   grid: (8, B)
__global__ void gate_split_kernel(float* __restrict__ s) {
    int b = blockIdx.y, t = threadIdx.x;
    float xg = (g_scores[b * CC + t] - g_thresh[b]) / TEMPR;
    float gt;
    if (xg >= 0.f) gt = 1.0f / (1.0f + expf(-xg));
    else { float ex = expf(xg); gt = ex / (1.0f + ex); }
    size_t base = ((size_t)b * NN_ + (size_t)blockIdx.x * 128) * CC;
    double e = 0.0;
    for (int r = 0; r < 128; r++) {
        size_t idx = base + (size_t)r * CC + t;
        float v = s[idx] * gt;
        s[idx] = v;
        float h, l;
        tf32_split(v, h, l);
        g_sN_hi[idx] = h; g_sN_lo[idx] = l;
        e += (double)(-v * logf(v + 1e-15f));
    }
    __shared__ double sm[256];
    double tot = block_red_d(e, sm);
    if (t == 0) atomicAdd(&g_ent, tot);
}

// per-batch traces / frobenius sums over [C,C] mats
__global__ void batchred_kernel(const float* __restrict__ adjp) {
    int b = blockIdx.x, t = threadIdx.x;
    const float* P = adjp  + (size_t)b * CC * CC;
    const float* G = g_sts + (size_t)b * CC * CC;
    const float* U = g_U   + (size_t)b * CC * CC;
    const float* V = g_V   + (size_t)b * CC * CC;
    double trA = 0, ssA = 0, trG = 0, ssG = 0, duv = 0;
    for (int i = t; i < CC * CC; i += 256) {
        float p = P[i]; ssA += (double)p * p;
        float g = G[i]; ssG += (double)g * g;
        duv += (double)U[i] * (double)V[i];
        if (i % (CC + 1) == 0) { trA += p; trG += g; }
    }
    __shared__ double sm[256];
    double r;
    r = block_red_d(trA, sm); if (t == 0) g_trA[b] = r;
    r = block_red_d(ssA, sm); if (t == 0) g_ssA[b] = r;
    r = block_red_d(trG, sm); if (t == 0) g_trG[b] = r;
    r = block_red_d(ssG, sm); if (t == 0) g_ssG[b] = r;
    r = block_red_d(duv, sm); if (t == 0) g_dotUV[b] = r;
}

__global__ void final_kernel(float* __restrict__ o) {
    double linksq = g_sumsq_adj, reconsq = g_sumsq_adj, clusum = 0.0;
    for (int b = 0; b < BB; b++) {
        linksq  += -2.0 * g_trA[b] + g_ssG[b];
        reconsq += -2.0 * g_ssA[b] + g_dotUV[b];
        double nrm = sqrt(g_ssG[b]); if (nrm < 1e-12) nrm = 1e-12;
        double t1 = g_ssG[b] / (nrm * nrm);
        double cb = t1 - 2.0 * g_trG[b] / (nrm * 16.0) + 1.0;   // sqrt(C)=16
        clusum += sqrt(cb > 0.0 ? cb : 0.0);
    }
    double sz = (double)BB * NN_ * NN_;
    o[0] = (float)(sqrt(linksq  > 0.0 ? linksq  : 0.0) / sz);  // link
    o[1] = (float)(g_ent / ((double)BB * NN_));                // ent
    o[2] = (float)(clusum / BB);                               // clu
    o[3] = (float)(sqrt(reconsq > 0.0 ? reconsq : 0.0) / sz);  // recon
}

// ---------------- launch ----------------
#define SYM(p, s) cudaGetSymbolAddress((void**)&p, s)

extern "C" void kernel_launch(void* const* d_in, const int* in_sizes, int n_in,
                              void* d_out, int out_size) {
    const float* x    = (const float*)d_in[0];
    const float* adj  = (const float*)d_in[1];
    const float* br_p = (const float*)d_in[3];
    const float* bl_p = (const float*)d_in[6];
    const float* br_e = (const float*)d_in[8];
    const float* bl_e = (const float*)d_in[11];

    float* out       = (float*)d_out;
    float* out_xp    = out;                         // [B,C,E]
    float* out_adjp  = out + 2097152;               // [B,C,C]
    float* out_s     = out + 4194304;               // [B,N,C]
    float* out_scal  = out + 12582912;              // link, ent, clu, recon
    float* out_nodex = out + 12582916;              // [B,N,E]

    float *adjNh, *xNh, *xNl, *aggNh, *aggNl, *hh, *hl;
    float *ndxh, *sNh, *sNl, *aTsh, *Wh;
    float *apNh, *apNl, *stsNh, *pre, *sts, *U, *V, *invdeg;
    SYM(adjNh, g_adjN_hi);
    SYM(xNh, g_xN_hi); SYM(xNl, g_xN_lo);
    SYM(aggNh, g_aggN_hi); SYM(aggNl, g_aggN_lo);
    SYM(hh, g_h_hi); SYM(hl, g_h_lo);
    SYM(ndxh, g_ndx_hi);
    SYM(sNh, g_sN_hi); SYM(sNl, g_sN_lo);
    SYM(aTsh, g_aTs_hi);
    SYM(Wh, g_W_hi);
    SYM(apNh, g_apN_hi); SYM(apNl, g_apN_lo);
    SYM(stsNh, g_stsN_hi);
    SYM(pre, g_pre); SYM(sts, g_sts); SYM(U, g_U); SYM(V, g_V);
    SYM(invdeg, g_invdeg);

    cudaFuncSetAttribute(gemm_tc<true, false>,  cudaFuncAttributeMaxDynamicSharedMemorySize, GSMEM_B);
    cudaFuncSetAttribute(gemm_tc<true, true>,   cudaFuncAttributeMaxDynamicSharedMemorySize, GSMEM_B);
    cudaFuncSetAttribute(gemm_tc<false, false>, cudaFuncAttributeMaxDynamicSharedMemorySize, GSMEM_B);
    cudaFuncSetAttribute(gemm_tc<false, true>,  cudaFuncAttributeMaxDynamicSharedMemorySize, GSMEM_B);

    init_kernel<<<32, 256>>>();

    // input splits
    nsplit_kernel<<<4096, 256>>>(x, xNh, xNl, 2097152);
    wsplit_kernel<<<dim3(64, 6), 256>>>(
        (const float*)d_in[2], (const float*)d_in[4], (const float*)d_in[5],
        (const float*)d_in[7], (const float*)d_in[9], (const float*)d_in[10]);
    split_adj_kernel<<<BB * NN_ / 8, 256>>>(adj);

    // agg = (adj @ x) * invdeg(row)   LOB: adj truncated, x hi+lo on B
    gemm_tc<true, true><<<dim3(2, 8, BB), 256, GSMEM_B>>>(
        adjNh, nullptr, xNh, xNl, nullptr, nullptr, nullptr, nullptr,
        nullptr, aggNh, aggNl, nullptr, invdeg,
        1024, 256, 256, 1024,
        (size_t)NN_ * NN_, (size_t)NN_ * DD, (size_t)NN_ * DD, NN_);

    // ---- embed branch ----
    gemm_tc<true, false><<<dim3(2, 256, 1), 256, GSMEM_B>>>(   // pre = agg@Wr_e + x@Wo_e + br_e
        aggNh, aggNl, Wh + 3 * 65536, nullptr,
        xNh, xNl, Wh + 4 * 65536, nullptr,
        pre, nullptr, nullptr, br_e, nullptr,
        256, 256, 256, 256, 0, 0, 0, 0);
    normrelu_split_kernel<<<BB * NN_, 256>>>();
    gemm_tc<true, false><<<dim3(2, 256, 1), 256, GSMEM_B>>>(   // nodex = h@Wl_e + bl_e
        hh, hl, Wh + 5 * 65536, nullptr,
        nullptr, nullptr, nullptr, nullptr,
        out_nodex, ndxh, nullptr, bl_e, nullptr,
        256, 256, 256, 256, 0, 0, 0, 0);

    // ---- pool branch ----
    gemm_tc<true, false><<<dim3(2, 256, 1), 256, GSMEM_B>>>(   // pre = agg@Wr_p + x@Wo_p + br_p
        aggNh, aggNl, Wh + 0 * 65536, nullptr,
        xNh, xNl, Wh + 1 * 65536, nullptr,
        pre, nullptr, nullptr, br_p, nullptr,
        256, 256, 256, 256, 0, 0, 0, 0);
    normrelu_split_kernel<<<BB * NN_, 256>>>();
    gemm_tc<true, false><<<dim3(2, 256, 1), 256, GSMEM_B>>>(   // logits = h@Wl_p + bl_p
        hh, hl, Wh + 2 * 65536, nullptr,
        nullptr, nullptr, nullptr, nullptr,
        out_s, nullptr, nullptr, bl_p, nullptr,
        256, 256, 256, 256, 0, 0, 0, 0);

    // softmax, scores, top-k gate (+entropy, +s planes)
    softmax_kernel<<<BB * NN_, 256>>>(out_s);
    colsum_kernel<<<dim3(8, BB), 256>>>(out_s);
    topk_kernel<<<BB, 256>>>();
    gate_split_kernel<<<dim3(8, BB), 256>>>(out_s);

    // xp = s^T @ nodex    (A = sN k-major, lo on A; ndx hi only)
    gemm_tc<false, false><<<dim3(2, 2, BB), 256, GSMEM_B>>>(
        sNh, sNl, ndxh, nullptr, nullptr, nullptr, nullptr, nullptr,
        out_xp, nullptr, nullptr, nullptr, nullptr,
        256, 256, 256, 1024,
        (size_t)NN_ * CC, (size_t)NN_ * EE, (size_t)CC * EE, 0);

    // aTs = adj^T @ s     (A = adjN k-major hi only; s hi+lo on B)
    gemm_tc<false, true><<<dim3(2, 8, BB), 256, GSMEM_B>>>(
        adjNh, nullptr, sNh, sNl, nullptr, nullptr, nullptr, nullptr,
        nullptr, aTsh, nullptr, nullptr, nullptr,
        1024, 256, 256, 1024,
        (size_t)NN_ * NN_, (size_t)NN_ * CC, (size_t)NN_ * CC, 0);

    // adj_p = aTs^T @ s   (A = aTs hi only; s hi+lo on B)
    gemm_tc<false, true><<<dim3(2, 2, BB), 256, GSMEM_B>>>(
        aTsh, nullptr, sNh, sNl, nullptr, nullptr, nullptr, nullptr,
        out_adjp, apNh, apNl, nullptr, nullptr,
        256, 256, 256, 1024,
        (size_t)NN_ * CC, (size_t)NN_ * CC, (size_t)CC * CC, 0);

    // sts = s^T @ s       (A = sN hi+lo; B = sN hi)
    gemm_tc<false, false><<<dim3(2, 2, BB), 256, GSMEM_B>>>(
        sNh, sNl, sNh, nullptr, nullptr, nullptr, nullptr, nullptr,
        sts, stsNh, nullptr, nullptr, nullptr,
        256, 256, 256, 1024,
        (size_t)NN_ * CC, (size_t)NN_ * CC, (size_t)CC * CC, 0);

    // U = adjp @ sts  (A = apN hi+lo; B = sts hi)
    gemm_tc<true, false><<<dim3(2, 2, BB), 256, GSMEM_B>>>(
        apNh, apNl, stsNh, nullptr, nullptr, nullptr, nullptr, nullptr,
        U, nullptr, nullptr, nullptr, nullptr,
        256, 256, 256, 256,
        (size_t)CC * CC, (size_t)CC * CC, (size_t)CC * CC, 0);
    // V = sts @ adjp  (A = sts hi only; B = apN hi+lo)
    gemm_tc<true, true><<<dim3(2, 2, BB), 256, GSMEM_B>>>(
        stsNh, nullptr, apNh, apNl, nullptr, nullptr, nullptr, nullptr,
        V, nullptr, nullptr, nullptr, nullptr,
        256, 256, 256, 256,
        (size_t)CC * CC, (size_t)CC * CC, (size_t)CC * CC, 0);

    // scalar losses
    batchred_kernel<<<BB, 256>>>(out_adjp);
    final_kernel<<<1, 1>>>(out_scal);
}